// round 14
// baseline (speedup 1.0000x reference)
#include <cuda_runtime.h>
#include <cuda_fp16.h>
#include <cstdint>
#include <math.h>

#define BB 64
#define NN 8192
#define SS 14
#define KN 10
#define DD 384
#define NSEQ (BB*KN)      /* 640  */
#define MM (NSEQ*SS)      /* 8960 */
#define NHH 8
#define HDD 48

/* ------------------------------------------------------------------ */
/* scratch (device globals: no allocation allowed)                     */
/* ------------------------------------------------------------------ */
__device__ float g_sim[BB*SS*NN];
__device__ int   g_idx[BB*SS*KN];
__device__ float g_x  [MM*DD];

__device__ __align__(16) __half g_hh   [MM*DD];
__device__ __align__(16) __half g_aoh  [MM*DD];
__device__ __align__(16) __half g_qh   [MM*DD];
__device__ __align__(16) __half g_memh [MM*DD];
__device__ __align__(16) __half g_mem2h[MM*DD];
__device__ __align__(16) __half g_ffh  [MM*1536];
__device__ __align__(16) __half g_qkvh [MM*1152];
__device__ __align__(16) __half g_kv3h [3][MM*768];

/* weights converted to half, once per launch */
__device__ __align__(16) __half g_wsa[6*1152*DD];
__device__ __align__(16) __half g_wso[6*DD*DD];
__device__ __align__(16) __half g_wca[6*1152*DD];
__device__ __align__(16) __half g_wco[6*DD*DD];
__device__ __align__(16) __half g_wf1[6*1536*DD];
__device__ __align__(16) __half g_wf2[6*DD*1536];

/* ------------------------------------------------------------------ */
/* fused weight conversion (all six tensors in one launch)             */
/* ------------------------------------------------------------------ */
#define C_WSA 663552   /* 6*1152*384/4 */
#define C_WSO 221184   /* 6*384*384/4  */
#define C_WF  884736   /* 6*1536*384/4 */
#define CVT_TOTAL (2*(C_WSA + C_WSO + C_WF))   /* float4 elements */
__global__ void cvtall_kernel(
    const float* __restrict__ sa_w, const float* __restrict__ sa_ow,
    const float* __restrict__ ca_w, const float* __restrict__ ca_ow,
    const float* __restrict__ f1w,  const float* __restrict__ f2w)
{
    long g = (long)blockIdx.x*256 + threadIdx.x;
    const float* s; __half* d; long o = g;
    if      (o < C_WSA)                       { s = sa_w;  d = g_wsa; }
    else if ((o -= C_WSA) < C_WSO)            { s = sa_ow; d = g_wso; }
    else if ((o -= C_WSO) < C_WSA)            { s = ca_w;  d = g_wca; }
    else if ((o -= C_WSA) < C_WSO)            { s = ca_ow; d = g_wco; }
    else if ((o -= C_WSO) < C_WF)             { s = f1w;   d = g_wf1; }
    else if ((o -= C_WF)  < C_WF)             { s = f2w;   d = g_wf2; }
    else return;
    float4 v = ((const float4*)s)[o];
    ((__half2*)d)[2*o]   = __floats2half2_rn(v.x, v.y);
    ((__half2*)d)[2*o+1] = __floats2half2_rn(v.z, v.w);
}

/* ------------------------------------------------------------------ */
/* 1) similarity (exact fp32 — protects top-k ordering)                */
/* ------------------------------------------------------------------ */
__global__ __launch_bounds__(128) void sim_kernel(
    const float* __restrict__ qt, const float* __restrict__ nd,
    float* __restrict__ sim)
{
    __shared__ float s_qt[SS*DD];
    __shared__ float s_nd[8][512];
    int b   = blockIdx.y;
    int n0  = blockIdx.x * 512;
    int tid = threadIdx.x;

    const float4* qtb = (const float4*)(qt + (long)b*SS*DD);
    for (int i = tid; i < SS*DD/4; i += 128)
        ((float4*)s_qt)[i] = qtb[i];

    float acc[14][4];
    #pragma unroll
    for (int h = 0; h < 14; h++)
        acc[h][0]=acc[h][1]=acc[h][2]=acc[h][3]=0.f;

    int lr = tid >> 1;
    int lk = (tid & 1) * 4;
    const float* ndb = nd + ((long)b*NN + n0)*DD;

    for (int k0 = 0; k0 < DD; k0 += 8) {
        __syncthreads();
        #pragma unroll
        for (int p = 0; p < 8; p++) {
            int r = p*64 + lr;
            float4 v = *(const float4*)(ndb + (long)r*DD + k0 + lk);
            s_nd[lk+0][r] = v.x; s_nd[lk+1][r] = v.y;
            s_nd[lk+2][r] = v.z; s_nd[lk+3][r] = v.w;
        }
        __syncthreads();
        #pragma unroll
        for (int k = 0; k < 8; k++) {
            float b0 = s_nd[k][tid];
            float b1 = s_nd[k][tid+128];
            float b2 = s_nd[k][tid+256];
            float b3 = s_nd[k][tid+384];
            #pragma unroll
            for (int h = 0; h < 14; h++) {
                float a = s_qt[h*DD + k0 + k];
                acc[h][0] = fmaf(a, b0, acc[h][0]);
                acc[h][1] = fmaf(a, b1, acc[h][1]);
                acc[h][2] = fmaf(a, b2, acc[h][2]);
                acc[h][3] = fmaf(a, b3, acc[h][3]);
            }
        }
    }
    #pragma unroll
    for (int h = 0; h < 14; h++) {
        float* srow = sim + ((long)(b*SS + h))*NN + n0;
        srow[tid]     = acc[h][0];
        srow[tid+128] = acc[h][1];
        srow[tid+256] = acc[h][2];
        srow[tid+384] = acc[h][3];
    }
}

/* ------------------------------------------------------------------ */
/* 2) top-k per (b,h) row                                              */
/* ------------------------------------------------------------------ */
__global__ __launch_bounds__(256) void topk_kernel(
    const float* __restrict__ sim, int* __restrict__ idx)
{
    __shared__ float sv[NN];
    __shared__ float rv[256];
    __shared__ int   ri[256];
    int row = blockIdx.x;
    int tid = threadIdx.x;
    const float* srow = sim + (long)row*NN;
    for (int j = tid; j < NN; j += 256) sv[j] = srow[j];
    __syncthreads();

    for (int it = 0; it < KN; it++) {
        float bv = -3.4e38f; int bi = 0;
        for (int j = tid; j < NN; j += 256) {
            float v = sv[j];
            if (v > bv) { bv = v; bi = j; }
        }
        rv[tid] = bv; ri[tid] = bi;
        __syncthreads();
        for (int s = 128; s > 0; s >>= 1) {
            if (tid < s) {
                float ov = rv[tid+s]; int oi = ri[tid+s];
                if (ov > rv[tid] || (ov == rv[tid] && oi < ri[tid])) {
                    rv[tid] = ov; ri[tid] = oi;
                }
            }
            __syncthreads();
        }
        if (tid == 0) {
            idx[row*KN + it] = ri[0];
            sv[ri[0]] = -3.4e38f;
        }
        __syncthreads();
    }
}

/* ------------------------------------------------------------------ */
/* 3) build: x0 f32 (broadcast qt), mem half (gathered nd rows)        */
/* ------------------------------------------------------------------ */
__global__ void build_kernel(
    const float* __restrict__ qt, const float* __restrict__ nd,
    const int* __restrict__ idx, float* __restrict__ x, __half* __restrict__ mem)
{
    int g = blockIdx.x*256 + threadIdx.x;
    int row = g / 96, c = g - row*96;
    int b  = row / (KN*SS);
    int rj = row - b*KN*SS;
    int j  = rj / SS, t = rj - j*SS;
    ((float4*)x)[g] = ((const float4*)qt)[(b*SS + t)*96 + c];
    int n = idx[(b*SS + t)*KN + j];
    float4 v = ((const float4*)nd)[((long)b*NN + n)*96 + c];
    ((__half2*)mem)[2*g]   = __floats2half2_rn(v.x, v.y);
    ((__half2*)mem)[2*g+1] = __floats2half2_rn(v.z, v.w);
}

/* ------------------------------------------------------------------ */
/* 4) LayerNorm: warp per row.                                         */
/*    MODE 0: f32 out   MODE 1: half out   MODE 2: f32 in-place + half */
/* ------------------------------------------------------------------ */
template<int MODE>
__global__ __launch_bounds__(256) void ln_kernel(
    const float* __restrict__ in, const float* __restrict__ w,
    const float* __restrict__ bias, void* __restrict__ outp,
    __half* __restrict__ outh2)
{
    int row  = blockIdx.x*8 + (threadIdx.x >> 5);
    int lane = threadIdx.x & 31;
    const float4* r4 = (const float4*)(in + (long)row*DD);
    float4 v0 = r4[lane], v1 = r4[lane+32], v2 = r4[lane+64];

    float s = v0.x+v0.y+v0.z+v0.w + v1.x+v1.y+v1.z+v1.w + v2.x+v2.y+v2.z+v2.w;
    #pragma unroll
    for (int o = 16; o; o >>= 1) s += __shfl_xor_sync(0xffffffffu, s, o);
    float mu = s * (1.0f/DD);

    float d, ds = 0.f;
    d=v0.x-mu; ds=fmaf(d,d,ds); d=v0.y-mu; ds=fmaf(d,d,ds);
    d=v0.z-mu; ds=fmaf(d,d,ds); d=v0.w-mu; ds=fmaf(d,d,ds);
    d=v1.x-mu; ds=fmaf(d,d,ds); d=v1.y-mu; ds=fmaf(d,d,ds);
    d=v1.z-mu; ds=fmaf(d,d,ds); d=v1.w-mu; ds=fmaf(d,d,ds);
    d=v2.x-mu; ds=fmaf(d,d,ds); d=v2.y-mu; ds=fmaf(d,d,ds);
    d=v2.z-mu; ds=fmaf(d,d,ds); d=v2.w-mu; ds=fmaf(d,d,ds);
    #pragma unroll
    for (int o = 16; o; o >>= 1) ds += __shfl_xor_sync(0xffffffffu, ds, o);
    float r = rsqrtf(ds*(1.0f/DD) + 1e-5f);

    const float4* w4 = (const float4*)w;
    const float4* b4 = (const float4*)bias;
    #pragma unroll
    for (int k = 0; k < 3; k++) {
        float4 v = (k==0) ? v0 : (k==1) ? v1 : v2;
        float4 wv = w4[lane + k*32], bv = b4[lane + k*32];
        float ox = fmaf((v.x-mu)*r, wv.x, bv.x);
        float oy = fmaf((v.y-mu)*r, wv.y, bv.y);
        float oz = fmaf((v.z-mu)*r, wv.z, bv.z);
        float ow = fmaf((v.w-mu)*r, wv.w, bv.w);
        if (MODE == 1) {
            __half2* o2 = (__half2*)outp + (long)row*(DD/2) + lane*2 + k*64;
            o2[0] = __floats2half2_rn(ox, oy);
            o2[1] = __floats2half2_rn(oz, ow);
        } else {
            float4* o4 = (float4*)outp + (long)row*(DD/4) + lane + k*32;
            *o4 = make_float4(ox, oy, oz, ow);
            if (MODE == 2) {
                __half2* o2 = (__half2*)outh2 + (long)row*(DD/2) + lane*2 + k*64;
                o2[0] = __floats2half2_rn(ox, oy);
                o2[1] = __floats2half2_rn(oz, ow);
            }
        }
    }
}

/* ------------------------------------------------------------------ */
/* 5) fp16 mma.sync GEMM core, BK=32, 4-stage cp.async, ldmatrix.      */
/*    128x128x32 tile, 256 thr, warp 64x32, m16n8k16.                  */
/*    Dynamic smem: 4 stages x (8KB A + 8KB B) = 64KB; 2 CTAs/SM.      */
/* ------------------------------------------------------------------ */
#define LDSM4(d0,d1,d2,d3,a) \
    asm volatile("ldmatrix.sync.aligned.m8n8.x4.shared.b16 {%0,%1,%2,%3}, [%4];" \
        : "=r"(d0),"=r"(d1),"=r"(d2),"=r"(d3) : "r"(a))

#define CP16(dst, src) \
    asm volatile("cp.async.cg.shared.global [%0], [%1], 16;" \
        :: "r"(dst), "l"(src))
#define CP_COMMIT() asm volatile("cp.async.commit_group;")
#define CP_WAIT2()  asm volatile("cp.async.wait_group 2;")

#define STG_B   8192u            /* bytes per stage per matrix */
#define B_OFF   (4*STG_B)        /* B region offset (A: 4 stages first) */
#define HG_SMEM (8*STG_B)        /* 64 KB */

__device__ __forceinline__ void mma_f16(
    float* c, const uint32_t* a, uint32_t b0, uint32_t b1)
{
    asm volatile(
        "mma.sync.aligned.m16n8k16.row.col.f32.f16.f16.f32 "
        "{%0,%1,%2,%3}, {%4,%5,%6,%7}, {%8,%9}, {%0,%1,%2,%3};"
        : "+f"(c[0]), "+f"(c[1]), "+f"(c[2]), "+f"(c[3])
        : "r"(a[0]), "r"(a[1]), "r"(a[2]), "r"(a[3]), "r"(b0), "r"(b1));
}

template<int DO_GELU, int DO_RES, int OUT_HALF>
__device__ __forceinline__ void gemm_core(
    const __half* __restrict__ A, const __half* __restrict__ B,
    const float* __restrict__ bias, const float* __restrict__ res,
    void* __restrict__ Cout, int N, int K, int m0, int n0, char* dsm)
{
    int tid = threadIdx.x, lane = tid & 31, wid = tid >> 5;
    int wm = wid >> 2, wn = wid & 3;
    int gid = lane >> 2, tig = lane & 3;

    /* staging: thread -> row r, chunks cp, cp+1 (16B each, 4 per row) */
    int r  = tid >> 1;
    int cp = (tid & 1) * 2;
    const __half* ap = A + (long)(m0 + r)*K + cp*8;
    const __half* bp = B + (long)(n0 + r)*K + cp*8;
    int sw  = (r >> 1) & 3;
    int sA0 = r*4 + (cp ^ sw), sA1 = r*4 + ((cp+1) ^ sw);
    uint32_t dA0 = (uint32_t)__cvta_generic_to_shared(dsm + sA0*16);
    uint32_t dA1 = (uint32_t)__cvta_generic_to_shared(dsm + sA1*16);
    uint32_t dB0 = dA0 + B_OFF;
    uint32_t dB1 = dA1 + B_OFF;

    /* ldmatrix base addresses (stage 0, ks=0); ks=1 via XOR 32 */
    uint32_t a_addr[4], b_addr[2];
    {
        int rr = (lane & 15), ch = (lane >> 4);
        #pragma unroll
        for (int mt = 0; mt < 4; mt++) {
            int row = wm*64 + mt*16 + rr;
            a_addr[mt] = (uint32_t)__cvta_generic_to_shared(
                dsm + (row*4 + (ch ^ ((row>>1)&3)))*16);
        }
        #pragma unroll
        for (int nt2 = 0; nt2 < 2; nt2++) {
            int row = wn*32 + nt2*16 + rr;
            b_addr[nt2] = (uint32_t)__cvta_generic_to_shared(
                dsm + (row*4 + (ch ^ ((row>>1)&3)))*16) + B_OFF;
        }
    }

    float acc[4][4][4];
    #pragma unroll
    for (int i = 0; i < 4; i++)
        #pragma unroll
        for (int j = 0; j < 4; j++)
            acc[i][j][0]=acc[i][j][1]=acc[i][j][2]=acc[i][j][3]=0.f;

    int nit = K >> 5;
    /* prologue: chunks 0,1,2 -> stages 0,1,2 */
    #pragma unroll
    for (int pc = 0; pc < 3; pc++) {
        uint32_t so = pc * STG_B;
        const __half* an = ap + pc*32;
        const __half* bn = bp + pc*32;
        CP16(dA0 + so, an); CP16(dA1 + so, an + 8);
        CP16(dB0 + so, bn); CP16(dB1 + so, bn + 8);
        CP_COMMIT();
    }

    int st = 0, stw = 3;
    for (int it = 0; it < nit; it++) {
        CP_WAIT2();            /* chunk `it` resident (<=2 outstanding) */
        __syncthreads();       /* orders reuse of stage stw (read it-1) */
        if (it + 3 < nit) {
            const __half* an = ap + (it+3)*32;
            const __half* bn = bp + (it+3)*32;
            uint32_t so = (uint32_t)(stw * STG_B);
            CP16(dA0 + so, an); CP16(dA1 + so, an + 8);
            CP16(dB0 + so, bn); CP16(dB1 + so, bn + 8);
        }
        CP_COMMIT();           /* keep group accounting aligned */

        uint32_t coff = (uint32_t)(st * STG_B);
        #pragma unroll
        for (int ks = 0; ks < 2; ks++) {
            uint32_t kb = (uint32_t)(ks * 32);
            uint32_t af[4][4], bf[4][2];
            #pragma unroll
            for (int mt = 0; mt < 4; mt++)
                LDSM4(af[mt][0], af[mt][1], af[mt][2], af[mt][3],
                      (a_addr[mt] + coff) ^ kb);
            #pragma unroll
            for (int nt2 = 0; nt2 < 2; nt2++) {
                uint32_t r0,r1,r2,r3;
                LDSM4(r0, r1, r2, r3, (b_addr[nt2] + coff) ^ kb);
                bf[nt2*2+0][0] = r0; bf[nt2*2+0][1] = r2;
                bf[nt2*2+1][0] = r1; bf[nt2*2+1][1] = r3;
            }
            #pragma unroll
            for (int mt = 0; mt < 4; mt++)
                #pragma unroll
                for (int nt = 0; nt < 4; nt++)
                    mma_f16(acc[mt][nt], af[mt], bf[nt][0], bf[nt][1]);
        }
        st  = (st  + 1) & 3;
        stw = (stw + 1) & 3;
    }

    /* epilogue */
    #pragma unroll
    for (int mt = 0; mt < 4; mt++) {
        int r0r = m0 + wm*64 + mt*16 + gid;
        #pragma unroll
        for (int nt = 0; nt < 4; nt++) {
            int cb = n0 + wn*32 + nt*8 + tig*2;
            float bb0 = bias[cb], bb1 = bias[cb+1];
            float v00 = acc[mt][nt][0] + bb0, v01 = acc[mt][nt][1] + bb1;
            float v10 = acc[mt][nt][2] + bb0, v11 = acc[mt][nt][3] + bb1;
            if (DO_GELU) {
                v00 = 0.5f*v00*(1.0f + erff(v00*0.70710678118654752f));
                v01 = 0.5f*v01*(1.0f + erff(v01*0.70710678118654752f));
                v10 = 0.5f*v10*(1.0f + erff(v10*0.70710678118654752f));
                v11 = 0.5f*v11*(1.0f + erff(v11*0.70710678118654752f));
            }
            long o0 = (long)r0r*N + cb;
            long o1 = (long)(r0r+8)*N + cb;
            if (DO_RES) {
                float2 q0 = *(const float2*)(res + o0);
                float2 q1 = *(const float2*)(res + o1);
                v00 += q0.x; v01 += q0.y; v10 += q1.x; v11 += q1.y;
            }
            if (OUT_HALF) {
                __half2* Ch = (__half2*)Cout;
                Ch[o0 >> 1] = __floats2half2_rn(v00, v01);
                Ch[o1 >> 1] = __floats2half2_rn(v10, v11);
            } else {
                float* Cf = (float*)Cout;
                *(float2*)(Cf + o0) = make_float2(v00, v01);
                *(float2*)(Cf + o1) = make_float2(v10, v11);
            }
        }
    }
}

template<int DO_GELU, int DO_RES, int OUT_HALF>
__global__ __launch_bounds__(256,2) void hgemm(
    const __half* __restrict__ A, const __half* __restrict__ B,
    const float* __restrict__ bias, const float* __restrict__ res,
    void* __restrict__ Cout, int N, int K)
{
    extern __shared__ __align__(128) char dsm[];
    gemm_core<DO_GELU,DO_RES,OUT_HALF>(A, B, bias, res, Cout, N, K,
                                       blockIdx.y << 7, blockIdx.x << 7, dsm);
}

/* batched kv projections for 3 layers (half output): 1260 blocks.     */
__global__ __launch_bounds__(256,2) void hgemm_kv(
    const __half* __restrict__ memory,
    const __half* __restrict__ wca_all,
    const float* __restrict__ ca_b,
    __half* __restrict__ kv3,
    int l0)
{
    extern __shared__ __align__(128) char dsm[];
    int bx = blockIdx.x;
    int l  = bx / 420, rr = bx - l*420;
    int n0 = (rr % 6) << 7, m0 = (rr / 6) << 7;
    const __half* B   = wca_all + (long)(l0+l)*1152*DD + (long)384*DD;
    const float*  bb  = ca_b + (l0+l)*1152 + 384;
    __half* C = kv3 + (long)l*MM*768;
    gemm_core<0,0,1>(memory, B, bb, (const float*)0, C, 768, DD, m0, n0, dsm);
}

/* ------------------------------------------------------------------ */
/* 6) attention: 4 warps/block, one (seq,head) per warp; half in/out.  */
/* ------------------------------------------------------------------ */
__global__ __launch_bounds__(128) void attn_kernel(
    const __half* __restrict__ qp, int qld,
    const __half* __restrict__ kp, int kld,
    const __half* __restrict__ vp, int vld,
    __half* __restrict__ op)
{
    __shared__ __align__(16) float sq [4][SS*HDD];
    __shared__ __align__(16) float sk [4][SS*HDD];
    __shared__ __align__(16) float svv[4][SS*HDD];
    __shared__ float sc[4][SS*16];
    int w    = threadIdx.x >> 5;
    int lane = threadIdx.x & 31;
    int pair = blockIdx.x*4 + w;
    int seq  = pair >> 3, h = pair & 7;
    int base = seq*SS;
    int hoff = h*HDD;

    for (int i2 = lane; i2 < SS*HDD/2; i2 += 32) {
        int e2 = i2*2;
        int t = e2 / HDD, e = e2 - t*HDD;
        float2 fq = __half22float2(*(const __half2*)(qp + (long)(base+t)*qld + hoff + e));
        float2 fk = __half22float2(*(const __half2*)(kp + (long)(base+t)*kld + hoff + e));
        float2 fv = __half22float2(*(const __half2*)(vp + (long)(base+t)*vld + hoff + e));
        sq [w][t*HDD+e] = fq.x; sq [w][t*HDD+e+1] = fq.y;
        sk [w][t*HDD+e] = fk.x; sk [w][t*HDD+e+1] = fk.y;
        svv[w][t*HDD+e] = fv.x; svv[w][t*HDD+e+1] = fv.y;
    }
    __syncwarp();

    const float scale = 0.14433756729740644f;   /* 1/sqrt(48) */
    for (int i = lane; i < SS*SS; i += 32) {
        int t = i / SS, u = i - t*SS;
        const float4* a4 = (const float4*)(sq[w] + t*HDD);
        const float4* b4 = (const float4*)(sk[w] + u*HDD);
        float s = 0.f;
        #pragma unroll
        for (int g = 0; g < 12; g++) {
            float4 a = a4[g], b = b4[g];
            s = fmaf(a.x,b.x,s); s = fmaf(a.y,b.y,s);
            s = fmaf(a.z,b.z,s); s = fmaf(a.w,b.w,s);
        }
        sc[w][t*16 + u] = s * scale;
    }
    __syncwarp();

    if (lane < SS) {
        float m = -3.4e38f;
        #pragma unroll
        for (int u = 0; u < SS; u++) m = fmaxf(m, sc[w][lane*16+u]);
        float sum = 0.f;
        #pragma unroll
        for (int u = 0; u < SS; u++) {
            float e = expf(sc[w][lane*16+u] - m);
            sc[w][lane*16+u] = e; sum += e;
        }
        float inv = 1.0f/sum;
        #pragma unroll
        for (int u = 0; u < SS; u++) sc[w][lane*16+u] *= inv;
    }
    __syncwarp();

    for (int i = lane; i < SS*HDD; i += 32) {
        int t = i / HDD, e = i - t*HDD;
        float o = 0.f;
        #pragma unroll
        for (int u = 0; u < SS; u++)
            o = fmaf(sc[w][t*16+u], svv[w][u*HDD+e], o);
        op[(long)(base+t)*DD + hoff + e] = __float2half(o);
    }
}

/* ------------------------------------------------------------------ */
/* host orchestration                                                  */
/* ------------------------------------------------------------------ */
extern "C" void kernel_launch(void* const* d_in, const int* in_sizes, int n_in,
                              void* d_out, int out_size)
{
    const float* qt    = (const float*)d_in[0];
    const float* nd    = (const float*)d_in[1];
    const float* sa_w  = (const float*)d_in[2];
    const float* sa_b  = (const float*)d_in[3];
    const float* sa_ow = (const float*)d_in[4];
    const float* sa_ob = (const float*)d_in[5];
    const float* ca_w  = (const float*)d_in[6];
    const float* ca_b  = (const float*)d_in[7];
    const float* ca_ow = (const float*)d_in[8];
    const float* ca_ob = (const float*)d_in[9];
    const float* ln1w  = (const float*)d_in[10];
    const float* ln1b  = (const float*)d_in[11];
    const float* ln2w  = (const float*)d_in[12];
    const float* ln2b  = (const float*)d_in[13];
    const float* ln3w  = (const float*)d_in[14];
    const float* ln3b  = (const float*)d_in[15];
    const float* f1w   = (const float*)d_in[16];
    const float* f1b   = (const float*)d_in[17];
    const float* f2w   = (const float*)d_in[18];
    const float* f2b   = (const float*)d_in[19];
    const float* fnw   = (const float*)d_in[20];
    const float* fnb   = (const float*)d_in[21];
    float* out = (float*)d_out;

    float *sim,*x; int* idx;
    __half *hh,*aoh,*qh,*memh,*mem2h,*ffh,*qkvh,*kv3h;
    __half *wsa,*wso,*wca,*wco,*wf1,*wf2;
    cudaGetSymbolAddress((void**)&sim,   g_sim);
    cudaGetSymbolAddress((void**)&idx,   g_idx);
    cudaGetSymbolAddress((void**)&x,     g_x);
    cudaGetSymbolAddress((void**)&hh,    g_hh);
    cudaGetSymbolAddress((void**)&aoh,   g_aoh);
    cudaGetSymbolAddress((void**)&qh,    g_qh);
    cudaGetSymbolAddress((void**)&memh,  g_memh);
    cudaGetSymbolAddress((void**)&mem2h, g_mem2h);
    cudaGetSymbolAddress((void**)&ffh,   g_ffh);
    cudaGetSymbolAddress((void**)&qkvh,  g_qkvh);
    cudaGetSymbolAddress((void**)&kv3h,  g_kv3h);
    cudaGetSymbolAddress((void**)&wsa,   g_wsa);
    cudaGetSymbolAddress((void**)&wso,   g_wso);
    cudaGetSymbolAddress((void**)&wca,   g_wca);
    cudaGetSymbolAddress((void**)&wco,   g_wco);
    cudaGetSymbolAddress((void**)&wf1,   g_wf1);
    cudaGetSymbolAddress((void**)&wf2,   g_wf2);

    /* raise dynamic smem limit (64 KB); idempotent, capture-safe */
    cudaFuncSetAttribute(hgemm<0,0,1>, cudaFuncAttributeMaxDynamicSharedMemorySize, HG_SMEM);
    cudaFuncSetAttribute(hgemm<0,1,0>, cudaFuncAttributeMaxDynamicSharedMemorySize, HG_SMEM);
    cudaFuncSetAttribute(hgemm<1,0,1>, cudaFuncAttributeMaxDynamicSharedMemorySize, HG_SMEM);
    cudaFuncSetAttribute(hgemm_kv,     cudaFuncAttributeMaxDynamicSharedMemorySize, HG_SMEM);

    /* weight conversion (once per launch, single kernel) */
    cvtall_kernel<<<(CVT_TOTAL + 255)/256, 256>>>(sa_w, sa_ow, ca_w, ca_ow, f1w, f2w);

    /* stage A: retrieval */
    sim_kernel  <<<dim3(16,64), 128>>>(qt, nd, sim);
    topk_kernel <<<BB*SS, 256>>>(sim, idx);
    build_kernel<<<3360, 256>>>(qt, nd, idx, x, memh);

    /* hoisted kv projections for layers 0-2 (dense 1260-CTA launch) */
    hgemm_kv<<<1260,256,HG_SMEM>>>(memh, wca, ca_b, kv3h, 0);

    /* stage B: 6 decoder blocks */
    for (int i = 0; i < 6; i++) {
        __half* kvl = kv3h + (long)(i % 3)*MM*768;

        /* self-attention */
        ln_kernel<1><<<1120,256>>>(x, ln1w + i*DD, ln1b + i*DD, hh, (__half*)0);
        hgemm<0,0,1><<<dim3(9,70),256,HG_SMEM>>>(hh, wsa + (long)i*1152*DD,
                                                 sa_b + i*1152, (const float*)0,
                                                 qkvh, 1152, DD);
        attn_kernel<<<1280,128>>>(qkvh,1152, qkvh+384,1152, qkvh+768,1152, aoh);
        hgemm<0,1,0><<<dim3(3,70),256,HG_SMEM>>>(aoh, wso + (long)i*DD*DD,
                                                 sa_ob + i*DD, x, x, DD, DD);

        /* cross-attention: q projection (kv already computed) */
        ln_kernel<1><<<1120,256>>>(x, ln2w + i*DD, ln2b + i*DD, hh, (__half*)0);
        hgemm<0,0,1><<<dim3(3,70),256,HG_SMEM>>>(hh, wca + (long)i*1152*DD,
                                                 ca_b + i*1152, (const float*)0,
                                                 qh, DD, DD);
        attn_kernel<<<1280,128>>>(qh,384, kvl,768, kvl+384,768, aoh);
        hgemm<0,1,0><<<dim3(3,70),256,HG_SMEM>>>(aoh, wco + (long)i*DD*DD,
                                                 ca_ob + i*DD, x, x, DD, DD);

        /* FFN */
        ln_kernel<1><<<1120,256>>>(x, ln3w + i*DD, ln3b + i*DD, hh, (__half*)0);
        hgemm<1,0,1><<<dim3(12,70),256,HG_SMEM>>>(hh, wf1 + (long)i*1536*DD,
                                                  f1b + i*1536, (const float*)0,
                                                  ffh, 1536, DD);
        hgemm<0,1,0><<<dim3(3,70),256,HG_SMEM>>>(ffh, wf2 + (long)i*DD*1536,
                                                 f2b + i*DD, x, x, DD, 1536);

        /* mid-stack snapshot + kv projections for layers 3-5 */
        if (i == 2) {
            ln_kernel<2><<<1120,256>>>(x, fnw, fnb, x, mem2h);
            hgemm_kv<<<1260,256,HG_SMEM>>>(mem2h, wca, ca_b, kv3h, 3);
        }
    }

    /* final norm straight into d_out (f32) */
    ln_kernel<0><<<1120,256>>>(x, fnw + DD, fnb + DD, out, (__half*)0);
}

// round 15
// speedup vs baseline: 1.0116x; 1.0116x over previous
#include <cuda_runtime.h>
#include <cuda_fp16.h>
#include <cstdint>
#include <math.h>

#define BB 64
#define NN 8192
#define SS 14
#define KN 10
#define DD 384
#define NSEQ (BB*KN)      /* 640  */
#define MM (NSEQ*SS)      /* 8960 */
#define NHH 8
#define HDD 48

/* ------------------------------------------------------------------ */
/* scratch (device globals: no allocation allowed)                     */
/* ------------------------------------------------------------------ */
__device__ float g_sim[BB*SS*NN];
__device__ int   g_idx[BB*SS*KN];
__device__ float g_x  [MM*DD];

__device__ __align__(16) __half g_hh   [MM*DD];
__device__ __align__(16) __half g_aoh  [MM*DD];
__device__ __align__(16) __half g_qh   [MM*DD];
__device__ __align__(16) __half g_memh [MM*DD];
__device__ __align__(16) __half g_mem2h[MM*DD];
__device__ __align__(16) __half g_ffh  [MM*1536];
__device__ __align__(16) __half g_qkvh [MM*1152];
__device__ __align__(16) __half g_kv3h [3][MM*768];

/* weights converted to half, once per launch */
__device__ __align__(16) __half g_wsa[6*1152*DD];
__device__ __align__(16) __half g_wso[6*DD*DD];
__device__ __align__(16) __half g_wca[6*1152*DD];
__device__ __align__(16) __half g_wco[6*DD*DD];
__device__ __align__(16) __half g_wf1[6*1536*DD];
__device__ __align__(16) __half g_wf2[6*DD*1536];

/* ------------------------------------------------------------------ */
/* fused weight conversion (all six tensors in one launch)             */
/* ------------------------------------------------------------------ */
#define C_WSA 663552   /* 6*1152*384/4 */
#define C_WSO 221184   /* 6*384*384/4  */
#define C_WF  884736   /* 6*1536*384/4 */
#define CVT_TOTAL (2*(C_WSA + C_WSO + C_WF))   /* float4 elements */
__global__ void cvtall_kernel(
    const float* __restrict__ sa_w, const float* __restrict__ sa_ow,
    const float* __restrict__ ca_w, const float* __restrict__ ca_ow,
    const float* __restrict__ f1w,  const float* __restrict__ f2w)
{
    long g = (long)blockIdx.x*256 + threadIdx.x;
    const float* s; __half* d; long o = g;
    if      (o < C_WSA)                       { s = sa_w;  d = g_wsa; }
    else if ((o -= C_WSA) < C_WSO)            { s = sa_ow; d = g_wso; }
    else if ((o -= C_WSO) < C_WSA)            { s = ca_w;  d = g_wca; }
    else if ((o -= C_WSA) < C_WSO)            { s = ca_ow; d = g_wco; }
    else if ((o -= C_WSO) < C_WF)             { s = f1w;   d = g_wf1; }
    else if ((o -= C_WF)  < C_WF)             { s = f2w;   d = g_wf2; }
    else return;
    float4 v = ((const float4*)s)[o];
    ((__half2*)d)[2*o]   = __floats2half2_rn(v.x, v.y);
    ((__half2*)d)[2*o+1] = __floats2half2_rn(v.z, v.w);
}

/* ------------------------------------------------------------------ */
/* 1) similarity (exact fp32 — protects top-k ordering)                */
/* ------------------------------------------------------------------ */
__global__ __launch_bounds__(128) void sim_kernel(
    const float* __restrict__ qt, const float* __restrict__ nd,
    float* __restrict__ sim)
{
    __shared__ float s_qt[SS*DD];
    __shared__ float s_nd[8][512];
    int b   = blockIdx.y;
    int n0  = blockIdx.x * 512;
    int tid = threadIdx.x;

    const float4* qtb = (const float4*)(qt + (long)b*SS*DD);
    for (int i = tid; i < SS*DD/4; i += 128)
        ((float4*)s_qt)[i] = qtb[i];

    float acc[14][4];
    #pragma unroll
    for (int h = 0; h < 14; h++)
        acc[h][0]=acc[h][1]=acc[h][2]=acc[h][3]=0.f;

    int lr = tid >> 1;
    int lk = (tid & 1) * 4;
    const float* ndb = nd + ((long)b*NN + n0)*DD;

    for (int k0 = 0; k0 < DD; k0 += 8) {
        __syncthreads();
        #pragma unroll
        for (int p = 0; p < 8; p++) {
            int r = p*64 + lr;
            float4 v = *(const float4*)(ndb + (long)r*DD + k0 + lk);
            s_nd[lk+0][r] = v.x; s_nd[lk+1][r] = v.y;
            s_nd[lk+2][r] = v.z; s_nd[lk+3][r] = v.w;
        }
        __syncthreads();
        #pragma unroll
        for (int k = 0; k < 8; k++) {
            float b0 = s_nd[k][tid];
            float b1 = s_nd[k][tid+128];
            float b2 = s_nd[k][tid+256];
            float b3 = s_nd[k][tid+384];
            #pragma unroll
            for (int h = 0; h < 14; h++) {
                float a = s_qt[h*DD + k0 + k];
                acc[h][0] = fmaf(a, b0, acc[h][0]);
                acc[h][1] = fmaf(a, b1, acc[h][1]);
                acc[h][2] = fmaf(a, b2, acc[h][2]);
                acc[h][3] = fmaf(a, b3, acc[h][3]);
            }
        }
    }
    #pragma unroll
    for (int h = 0; h < 14; h++) {
        float* srow = sim + ((long)(b*SS + h))*NN + n0;
        srow[tid]     = acc[h][0];
        srow[tid+128] = acc[h][1];
        srow[tid+256] = acc[h][2];
        srow[tid+384] = acc[h][3];
    }
}

/* ------------------------------------------------------------------ */
/* 2) top-k per (b,h) row                                              */
/* ------------------------------------------------------------------ */
__global__ __launch_bounds__(256) void topk_kernel(
    const float* __restrict__ sim, int* __restrict__ idx)
{
    __shared__ float sv[NN];
    __shared__ float rv[256];
    __shared__ int   ri[256];
    int row = blockIdx.x;
    int tid = threadIdx.x;
    const float* srow = sim + (long)row*NN;
    for (int j = tid; j < NN; j += 256) sv[j] = srow[j];
    __syncthreads();

    for (int it = 0; it < KN; it++) {
        float bv = -3.4e38f; int bi = 0;
        for (int j = tid; j < NN; j += 256) {
            float v = sv[j];
            if (v > bv) { bv = v; bi = j; }
        }
        rv[tid] = bv; ri[tid] = bi;
        __syncthreads();
        for (int s = 128; s > 0; s >>= 1) {
            if (tid < s) {
                float ov = rv[tid+s]; int oi = ri[tid+s];
                if (ov > rv[tid] || (ov == rv[tid] && oi < ri[tid])) {
                    rv[tid] = ov; ri[tid] = oi;
                }
            }
            __syncthreads();
        }
        if (tid == 0) {
            idx[row*KN + it] = ri[0];
            sv[ri[0]] = -3.4e38f;
        }
        __syncthreads();
    }
}

/* ------------------------------------------------------------------ */
/* 3) build: x0 f32 (broadcast qt), mem half (gathered nd rows)        */
/* ------------------------------------------------------------------ */
__global__ void build_kernel(
    const float* __restrict__ qt, const float* __restrict__ nd,
    const int* __restrict__ idx, float* __restrict__ x, __half* __restrict__ mem)
{
    int g = blockIdx.x*256 + threadIdx.x;
    int row = g / 96, c = g - row*96;
    int b  = row / (KN*SS);
    int rj = row - b*KN*SS;
    int j  = rj / SS, t = rj - j*SS;
    ((float4*)x)[g] = ((const float4*)qt)[(b*SS + t)*96 + c];
    int n = idx[(b*SS + t)*KN + j];
    float4 v = ((const float4*)nd)[((long)b*NN + n)*96 + c];
    ((__half2*)mem)[2*g]   = __floats2half2_rn(v.x, v.y);
    ((__half2*)mem)[2*g+1] = __floats2half2_rn(v.z, v.w);
}

/* ------------------------------------------------------------------ */
/* 4) LayerNorm: warp per row.                                         */
/*    MODE 0: f32 out   MODE 1: half out   MODE 2: f32 in-place + half */
/* ------------------------------------------------------------------ */
template<int MODE>
__global__ __launch_bounds__(256) void ln_kernel(
    const float* __restrict__ in, const float* __restrict__ w,
    const float* __restrict__ bias, void* __restrict__ outp,
    __half* __restrict__ outh2)
{
    int row  = blockIdx.x*8 + (threadIdx.x >> 5);
    int lane = threadIdx.x & 31;
    const float4* r4 = (const float4*)(in + (long)row*DD);
    float4 v0 = r4[lane], v1 = r4[lane+32], v2 = r4[lane+64];

    float s = v0.x+v0.y+v0.z+v0.w + v1.x+v1.y+v1.z+v1.w + v2.x+v2.y+v2.z+v2.w;
    #pragma unroll
    for (int o = 16; o; o >>= 1) s += __shfl_xor_sync(0xffffffffu, s, o);
    float mu = s * (1.0f/DD);

    float d, ds = 0.f;
    d=v0.x-mu; ds=fmaf(d,d,ds); d=v0.y-mu; ds=fmaf(d,d,ds);
    d=v0.z-mu; ds=fmaf(d,d,ds); d=v0.w-mu; ds=fmaf(d,d,ds);
    d=v1.x-mu; ds=fmaf(d,d,ds); d=v1.y-mu; ds=fmaf(d,d,ds);
    d=v1.z-mu; ds=fmaf(d,d,ds); d=v1.w-mu; ds=fmaf(d,d,ds);
    d=v2.x-mu; ds=fmaf(d,d,ds); d=v2.y-mu; ds=fmaf(d,d,ds);
    d=v2.z-mu; ds=fmaf(d,d,ds); d=v2.w-mu; ds=fmaf(d,d,ds);
    #pragma unroll
    for (int o = 16; o; o >>= 1) ds += __shfl_xor_sync(0xffffffffu, ds, o);
    float r = rsqrtf(ds*(1.0f/DD) + 1e-5f);

    const float4* w4 = (const float4*)w;
    const float4* b4 = (const float4*)bias;
    #pragma unroll
    for (int k = 0; k < 3; k++) {
        float4 v = (k==0) ? v0 : (k==1) ? v1 : v2;
        float4 wv = w4[lane + k*32], bv = b4[lane + k*32];
        float ox = fmaf((v.x-mu)*r, wv.x, bv.x);
        float oy = fmaf((v.y-mu)*r, wv.y, bv.y);
        float oz = fmaf((v.z-mu)*r, wv.z, bv.z);
        float ow = fmaf((v.w-mu)*r, wv.w, bv.w);
        if (MODE == 1) {
            __half2* o2 = (__half2*)outp + (long)row*(DD/2) + lane*2 + k*64;
            o2[0] = __floats2half2_rn(ox, oy);
            o2[1] = __floats2half2_rn(oz, ow);
        } else {
            float4* o4 = (float4*)outp + (long)row*(DD/4) + lane + k*32;
            *o4 = make_float4(ox, oy, oz, ow);
            if (MODE == 2) {
                __half2* o2 = (__half2*)outh2 + (long)row*(DD/2) + lane*2 + k*64;
                o2[0] = __floats2half2_rn(ox, oy);
                o2[1] = __floats2half2_rn(oz, ow);
            }
        }
    }
}

/* ------------------------------------------------------------------ */
/* 5) fp16 mma.sync GEMM core, BK=32, 3-stage cp.async, ldmatrix.      */
/*    128x128x32 tile, 256 thr, warp 64x32, m16n8k16. 48KB static.     */
/*    (R13-proven configuration.)                                      */
/* ------------------------------------------------------------------ */
#define LDSM4(d0,d1,d2,d3,a) \
    asm volatile("ldmatrix.sync.aligned.m8n8.x4.shared.b16 {%0,%1,%2,%3}, [%4];" \
        : "=r"(d0),"=r"(d1),"=r"(d2),"=r"(d3) : "r"(a))

#define CP16(dst, src) \
    asm volatile("cp.async.cg.shared.global [%0], [%1], 16;" \
        :: "r"(dst), "l"(src))
#define CP_COMMIT() asm volatile("cp.async.commit_group;")
#define CP_WAIT1()  asm volatile("cp.async.wait_group 1;")

__device__ __forceinline__ void mma_f16(
    float* c, const uint32_t* a, uint32_t b0, uint32_t b1)
{
    asm volatile(
        "mma.sync.aligned.m16n8k16.row.col.f32.f16.f16.f32 "
        "{%0,%1,%2,%3}, {%4,%5,%6,%7}, {%8,%9}, {%0,%1,%2,%3};"
        : "+f"(c[0]), "+f"(c[1]), "+f"(c[2]), "+f"(c[3])
        : "r"(a[0]), "r"(a[1]), "r"(a[2]), "r"(a[3]), "r"(b0), "r"(b1));
}

template<int DO_GELU, int DO_RES, int OUT_HALF>
__device__ __forceinline__ void gemm_core(
    const __half* __restrict__ A, const __half* __restrict__ B,
    const float* __restrict__ bias, const float* __restrict__ res,
    void* __restrict__ Cout, int N, int K, int m0, int n0)
{
    __shared__ __align__(128) uint4 As4[3][512];   /* 3 stages x 8KB */
    __shared__ __align__(128) uint4 Bs4[3][512];

    int tid = threadIdx.x, lane = tid & 31, wid = tid >> 5;
    int wm = wid >> 2, wn = wid & 3;
    int gid = lane >> 2, tig = lane & 3;

    int r  = tid >> 1;
    int cp = (tid & 1) * 2;
    const __half* ap = A + (long)(m0 + r)*K + cp*8;
    const __half* bp = B + (long)(n0 + r)*K + cp*8;
    int sw  = (r >> 1) & 3;
    int sA0 = r*4 + (cp ^ sw), sA1 = r*4 + ((cp+1) ^ sw);
    uint32_t dA0 = (uint32_t)__cvta_generic_to_shared(&As4[0][sA0]);
    uint32_t dA1 = (uint32_t)__cvta_generic_to_shared(&As4[0][sA1]);
    uint32_t dB0 = (uint32_t)__cvta_generic_to_shared(&Bs4[0][sA0]);
    uint32_t dB1 = (uint32_t)__cvta_generic_to_shared(&Bs4[0][sA1]);

    uint32_t a_addr[4], b_addr[2];
    {
        int rr = (lane & 15), ch = (lane >> 4);
        #pragma unroll
        for (int mt = 0; mt < 4; mt++) {
            int row = wm*64 + mt*16 + rr;
            a_addr[mt] = (uint32_t)__cvta_generic_to_shared(
                &As4[0][row*4 + (ch ^ ((row>>1)&3))]);
        }
        #pragma unroll
        for (int nt2 = 0; nt2 < 2; nt2++) {
            int row = wn*32 + nt2*16 + rr;
            b_addr[nt2] = (uint32_t)__cvta_generic_to_shared(
                &Bs4[0][row*4 + (ch ^ ((row>>1)&3))]);
        }
    }

    float acc[4][4][4];
    #pragma unroll
    for (int i = 0; i < 4; i++)
        #pragma unroll
        for (int j = 0; j < 4; j++)
            acc[i][j][0]=acc[i][j][1]=acc[i][j][2]=acc[i][j][3]=0.f;

    int nit = K >> 5;
    {
        CP16(dA0, ap);            CP16(dA1, ap + 8);
        CP16(dB0, bp);            CP16(dB1, bp + 8);
        CP_COMMIT();
        CP16(dA0 + 8192, ap + 32); CP16(dA1 + 8192, ap + 40);
        CP16(dB0 + 8192, bp + 32); CP16(dB1 + 8192, bp + 40);
        CP_COMMIT();
    }

    int st = 0, stw = 2;
    for (int it = 0; it < nit; it++) {
        CP_WAIT1();
        __syncthreads();
        if (it + 2 < nit) {
            const __half* an = ap + (it+2)*32;
            const __half* bn = bp + (it+2)*32;
            uint32_t so = (uint32_t)(stw * 8192);
            CP16(dA0 + so, an); CP16(dA1 + so, an + 8);
            CP16(dB0 + so, bn); CP16(dB1 + so, bn + 8);
        }
        CP_COMMIT();

        uint32_t coff = (uint32_t)(st * 8192);
        #pragma unroll
        for (int ks = 0; ks < 2; ks++) {
            uint32_t kb = (uint32_t)(ks * 32);
            uint32_t af[4][4], bf[4][2];
            #pragma unroll
            for (int mt = 0; mt < 4; mt++)
                LDSM4(af[mt][0], af[mt][1], af[mt][2], af[mt][3],
                      (a_addr[mt] + coff) ^ kb);
            #pragma unroll
            for (int nt2 = 0; nt2 < 2; nt2++) {
                uint32_t r0,r1,r2,r3;
                LDSM4(r0, r1, r2, r3, (b_addr[nt2] + coff) ^ kb);
                bf[nt2*2+0][0] = r0; bf[nt2*2+0][1] = r2;
                bf[nt2*2+1][0] = r1; bf[nt2*2+1][1] = r3;
            }
            #pragma unroll
            for (int mt = 0; mt < 4; mt++)
                #pragma unroll
                for (int nt = 0; nt < 4; nt++)
                    mma_f16(acc[mt][nt], af[mt], bf[nt][0], bf[nt][1]);
        }
        st  = (st  == 2) ? 0 : st  + 1;
        stw = (stw == 2) ? 0 : stw + 1;
    }

    /* epilogue */
    #pragma unroll
    for (int mt = 0; mt < 4; mt++) {
        int r0r = m0 + wm*64 + mt*16 + gid;
        #pragma unroll
        for (int nt = 0; nt < 4; nt++) {
            int cb = n0 + wn*32 + nt*8 + tig*2;
            float bb0 = bias[cb], bb1 = bias[cb+1];
            float v00 = acc[mt][nt][0] + bb0, v01 = acc[mt][nt][1] + bb1;
            float v10 = acc[mt][nt][2] + bb0, v11 = acc[mt][nt][3] + bb1;
            if (DO_GELU) {
                v00 = 0.5f*v00*(1.0f + erff(v00*0.70710678118654752f));
                v01 = 0.5f*v01*(1.0f + erff(v01*0.70710678118654752f));
                v10 = 0.5f*v10*(1.0f + erff(v10*0.70710678118654752f));
                v11 = 0.5f*v11*(1.0f + erff(v11*0.70710678118654752f));
            }
            long o0 = (long)r0r*N + cb;
            long o1 = (long)(r0r+8)*N + cb;
            if (DO_RES) {
                float2 q0 = *(const float2*)(res + o0);
                float2 q1 = *(const float2*)(res + o1);
                v00 += q0.x; v01 += q0.y; v10 += q1.x; v11 += q1.y;
            }
            if (OUT_HALF) {
                __half2* Ch = (__half2*)Cout;
                Ch[o0 >> 1] = __floats2half2_rn(v00, v01);
                Ch[o1 >> 1] = __floats2half2_rn(v10, v11);
            } else {
                float* Cf = (float*)Cout;
                *(float2*)(Cf + o0) = make_float2(v00, v01);
                *(float2*)(Cf + o1) = make_float2(v10, v11);
            }
        }
    }
}

template<int DO_GELU, int DO_RES, int OUT_HALF>
__global__ __launch_bounds__(256,2) void hgemm(
    const __half* __restrict__ A, const __half* __restrict__ B,
    const float* __restrict__ bias, const float* __restrict__ res,
    void* __restrict__ Cout, int N, int K)
{
    gemm_core<DO_GELU,DO_RES,OUT_HALF>(A, B, bias, res, Cout, N, K,
                                       blockIdx.y << 7, blockIdx.x << 7);
}

/* batched kv projections for 3 layers (half output): 1260 blocks.     */
__global__ __launch_bounds__(256,2) void hgemm_kv(
    const __half* __restrict__ memory,
    const __half* __restrict__ wca_all,
    const float* __restrict__ ca_b,
    __half* __restrict__ kv3,
    int l0)
{
    int bx = blockIdx.x;
    int l  = bx / 420, rr = bx - l*420;
    int n0 = (rr % 6) << 7, m0 = (rr / 6) << 7;
    const __half* B   = wca_all + (long)(l0+l)*1152*DD + (long)384*DD;
    const float*  bb  = ca_b + (l0+l)*1152 + 384;
    __half* C = kv3 + (long)l*MM*768;
    gemm_core<0,0,1>(memory, B, bb, (const float*)0, C, 768, DD, m0, n0);
}

/* ------------------------------------------------------------------ */
/* 6) attention: 4 warps/block, one (seq,head) per warp; half in/out.  */
/* ------------------------------------------------------------------ */
__global__ __launch_bounds__(128) void attn_kernel(
    const __half* __restrict__ qp, int qld,
    const __half* __restrict__ kp, int kld,
    const __half* __restrict__ vp, int vld,
    __half* __restrict__ op)
{
    __shared__ __align__(16) float sq [4][SS*HDD];
    __shared__ __align__(16) float sk [4][SS*HDD];
    __shared__ __align__(16) float svv[4][SS*HDD];
    __shared__ float sc[4][SS*16];
    int w    = threadIdx.x >> 5;
    int lane = threadIdx.x & 31;
    int pair = blockIdx.x*4 + w;
    int seq  = pair >> 3, h = pair & 7;
    int base = seq*SS;
    int hoff = h*HDD;

    for (int i2 = lane; i2 < SS*HDD/2; i2 += 32) {
        int e2 = i2*2;
        int t = e2 / HDD, e = e2 - t*HDD;
        float2 fq = __half22float2(*(const __half2*)(qp + (long)(base+t)*qld + hoff + e));
        float2 fk = __half22float2(*(const __half2*)(kp + (long)(base+t)*kld + hoff + e));
        float2 fv = __half22float2(*(const __half2*)(vp + (long)(base+t)*vld + hoff + e));
        sq [w][t*HDD+e] = fq.x; sq [w][t*HDD+e+1] = fq.y;
        sk [w][t*HDD+e] = fk.x; sk [w][t*HDD+e+1] = fk.y;
        svv[w][t*HDD+e] = fv.x; svv[w][t*HDD+e+1] = fv.y;
    }
    __syncwarp();

    const float scale = 0.14433756729740644f;   /* 1/sqrt(48) */
    for (int i = lane; i < SS*SS; i += 32) {
        int t = i / SS, u = i - t*SS;
        const float4* a4 = (const float4*)(sq[w] + t*HDD);
        const float4* b4 = (const float4*)(sk[w] + u*HDD);
        float s = 0.f;
        #pragma unroll
        for (int g = 0; g < 12; g++) {
            float4 a = a4[g], b = b4[g];
            s = fmaf(a.x,b.x,s); s = fmaf(a.y,b.y,s);
            s = fmaf(a.z,b.z,s); s = fmaf(a.w,b.w,s);
        }
        sc[w][t*16 + u] = s * scale;
    }
    __syncwarp();

    if (lane < SS) {
        float m = -3.4e38f;
        #pragma unroll
        for (int u = 0; u < SS; u++) m = fmaxf(m, sc[w][lane*16+u]);
        float sum = 0.f;
        #pragma unroll
        for (int u = 0; u < SS; u++) {
            float e = expf(sc[w][lane*16+u] - m);
            sc[w][lane*16+u] = e; sum += e;
        }
        float inv = 1.0f/sum;
        #pragma unroll
        for (int u = 0; u < SS; u++) sc[w][lane*16+u] *= inv;
    }
    __syncwarp();

    for (int i = lane; i < SS*HDD; i += 32) {
        int t = i / HDD, e = i - t*HDD;
        float o = 0.f;
        #pragma unroll
        for (int u = 0; u < SS; u++)
            o = fmaf(sc[w][t*16+u], svv[w][u*HDD+e], o);
        op[(long)(base+t)*DD + hoff + e] = __float2half(o);
    }
}

/* ------------------------------------------------------------------ */
/* host orchestration (fork/join streams for independent work)         */
/* ------------------------------------------------------------------ */
extern "C" void kernel_launch(void* const* d_in, const int* in_sizes, int n_in,
                              void* d_out, int out_size)
{
    const float* qt    = (const float*)d_in[0];
    const float* nd    = (const float*)d_in[1];
    const float* sa_w  = (const float*)d_in[2];
    const float* sa_b  = (const float*)d_in[3];
    const float* sa_ow = (const float*)d_in[4];
    const float* sa_ob = (const float*)d_in[5];
    const float* ca_w  = (const float*)d_in[6];
    const float* ca_b  = (const float*)d_in[7];
    const float* ca_ow = (const float*)d_in[8];
    const float* ca_ob = (const float*)d_in[9];
    const float* ln1w  = (const float*)d_in[10];
    const float* ln1b  = (const float*)d_in[11];
    const float* ln2w  = (const float*)d_in[12];
    const float* ln2b  = (const float*)d_in[13];
    const float* ln3w  = (const float*)d_in[14];
    const float* ln3b  = (const float*)d_in[15];
    const float* f1w   = (const float*)d_in[16];
    const float* f1b   = (const float*)d_in[17];
    const float* f2w   = (const float*)d_in[18];
    const float* f2b   = (const float*)d_in[19];
    const float* fnw   = (const float*)d_in[20];
    const float* fnb   = (const float*)d_in[21];
    float* out = (float*)d_out;

    float *sim,*x; int* idx;
    __half *hh,*aoh,*qh,*memh,*mem2h,*ffh,*qkvh,*kv3h;
    __half *wsa,*wso,*wca,*wco,*wf1,*wf2;
    cudaGetSymbolAddress((void**)&sim,   g_sim);
    cudaGetSymbolAddress((void**)&idx,   g_idx);
    cudaGetSymbolAddress((void**)&x,     g_x);
    cudaGetSymbolAddress((void**)&hh,    g_hh);
    cudaGetSymbolAddress((void**)&aoh,   g_aoh);
    cudaGetSymbolAddress((void**)&qh,    g_qh);
    cudaGetSymbolAddress((void**)&memh,  g_memh);
    cudaGetSymbolAddress((void**)&mem2h, g_mem2h);
    cudaGetSymbolAddress((void**)&ffh,   g_ffh);
    cudaGetSymbolAddress((void**)&qkvh,  g_qkvh);
    cudaGetSymbolAddress((void**)&kv3h,  g_kv3h);
    cudaGetSymbolAddress((void**)&wsa,   g_wsa);
    cudaGetSymbolAddress((void**)&wso,   g_wso);
    cudaGetSymbolAddress((void**)&wca,   g_wca);
    cudaGetSymbolAddress((void**)&wco,   g_wco);
    cudaGetSymbolAddress((void**)&wf1,   g_wf1);
    cudaGetSymbolAddress((void**)&wf2,   g_wf2);

    /* side streams + fork/join events (host-side only; not on replay path) */
    cudaStream_t s1, s2;
    cudaStreamCreateWithFlags(&s1, cudaStreamNonBlocking);
    cudaStreamCreateWithFlags(&s2, cudaStreamNonBlocking);
    cudaEvent_t evFork, evCvt, evBuild, evKV0, evSnap, evKV3;
    cudaEventCreateWithFlags(&evFork,  cudaEventDisableTiming);
    cudaEventCreateWithFlags(&evCvt,   cudaEventDisableTiming);
    cudaEventCreateWithFlags(&evBuild, cudaEventDisableTiming);
    cudaEventCreateWithFlags(&evKV0,   cudaEventDisableTiming);
    cudaEventCreateWithFlags(&evSnap,  cudaEventDisableTiming);
    cudaEventCreateWithFlags(&evKV3,   cudaEventDisableTiming);

    /* fork: weight conversion runs on s1, overlapped with retrieval */
    cudaEventRecord(evFork, 0);
    cudaStreamWaitEvent(s1, evFork, 0);
    cvtall_kernel<<<(CVT_TOTAL + 255)/256, 256, 0, s1>>>(
        sa_w, sa_ow, ca_w, ca_ow, f1w, f2w);
    cudaEventRecord(evCvt, s1);

    /* stage A: retrieval (default stream) */
    sim_kernel  <<<dim3(16,64), 128>>>(qt, nd, sim);
    topk_kernel <<<BB*SS, 256>>>(sim, idx);
    build_kernel<<<3360, 256>>>(qt, nd, idx, x, memh);
    cudaEventRecord(evBuild, 0);

    /* s2: kv projections layers 0-2 (needs memh + converted wca) */
    cudaStreamWaitEvent(s2, evBuild, 0);
    cudaStreamWaitEvent(s2, evCvt, 0);
    hgemm_kv<<<1260, 256, 0, s2>>>(memh, wca, ca_b, kv3h, 0);
    cudaEventRecord(evKV0, s2);

    /* default stream needs converted weights before first hgemm */
    cudaStreamWaitEvent(0, evCvt, 0);

    /* stage B: 6 decoder blocks */
    for (int i = 0; i < 6; i++) {
        __half* kvl = kv3h + (long)(i % 3)*MM*768;

        /* self-attention */
        ln_kernel<1><<<1120,256>>>(x, ln1w + i*DD, ln1b + i*DD, hh, (__half*)0);
        hgemm<0,0,1><<<dim3(9,70),256>>>(hh, wsa + (long)i*1152*DD,
                                         sa_b + i*1152, (const float*)0,
                                         qkvh, 1152, DD);
        attn_kernel<<<1280,128>>>(qkvh,1152, qkvh+384,1152, qkvh+768,1152, aoh);
        hgemm<0,1,0><<<dim3(3,70),256>>>(aoh, wso + (long)i*DD*DD,
                                         sa_ob + i*DD, x, x, DD, DD);

        /* cross-attention: q projection (kv computed on s2) */
        ln_kernel<1><<<1120,256>>>(x, ln2w + i*DD, ln2b + i*DD, hh, (__half*)0);
        hgemm<0,0,1><<<dim3(3,70),256>>>(hh, wca + (long)i*1152*DD,
                                         ca_b + i*1152, (const float*)0,
                                         qh, DD, DD);
        if (i == 0) cudaStreamWaitEvent(0, evKV0, 0);   /* join kv 0-2 */
        if (i == 3) cudaStreamWaitEvent(0, evKV3, 0);   /* join kv 3-5 */
        attn_kernel<<<1280,128>>>(qh,384, kvl,768, kvl+384,768, aoh);
        hgemm<0,1,0><<<dim3(3,70),256>>>(aoh, wco + (long)i*DD*DD,
                                         ca_ob + i*DD, x, x, DD, DD);

        /* FFN */
        ln_kernel<1><<<1120,256>>>(x, ln3w + i*DD, ln3b + i*DD, hh, (__half*)0);
        hgemm<1,0,1><<<dim3(12,70),256>>>(hh, wf1 + (long)i*1536*DD,
                                          f1b + i*1536, (const float*)0,
                                          ffh, 1536, DD);
        hgemm<0,1,0><<<dim3(3,70),256>>>(ffh, wf2 + (long)i*DD*1536,
                                         f2b + i*DD, x, x, DD, 1536);

        /* mid-stack snapshot; kv projections for layers 3-5 fork to s2 */
        if (i == 2) {
            ln_kernel<2><<<1120,256>>>(x, fnw, fnb, x, mem2h);
            cudaEventRecord(evSnap, 0);
            cudaStreamWaitEvent(s2, evSnap, 0);
            hgemm_kv<<<1260, 256, 0, s2>>>(mem2h, wca, ca_b, kv3h, 3);
            cudaEventRecord(evKV3, s2);
        }
    }

    /* final norm straight into d_out (f32) */
    ln_kernel<0><<<1120,256>>>(x, fnw + DD, fnb + DD, out, (__half*)0);

    cudaEventDestroy(evFork);  cudaEventDestroy(evCvt);
    cudaEventDestroy(evBuild); cudaEventDestroy(evKV0);
    cudaEventDestroy(evSnap);  cudaEventDestroy(evKV3);
    cudaStreamDestroy(s1);
    cudaStreamDestroy(s2);
}

// round 16
// speedup vs baseline: 1.0147x; 1.0030x over previous
#include <cuda_runtime.h>
#include <cuda_fp16.h>
#include <cstdint>
#include <math.h>

#define BB 64
#define NN 8192
#define SS 14
#define KN 10
#define DD 384
#define NSEQ (BB*KN)      /* 640  */
#define MM (NSEQ*SS)      /* 8960 */
#define NHH 8
#define HDD 48

/* ------------------------------------------------------------------ */
/* scratch (device globals: no allocation allowed)                     */
/* ------------------------------------------------------------------ */
__device__ float g_sim[BB*SS*NN];
__device__ int   g_idx[BB*SS*KN];
__device__ float g_x  [MM*DD];

__device__ __align__(16) __half g_hh   [MM*DD];
__device__ __align__(16) __half g_aoh  [MM*DD];
__device__ __align__(16) __half g_qh   [MM*DD];
__device__ __align__(16) __half g_memh [MM*DD];
__device__ __align__(16) __half g_mem2h[MM*DD];
__device__ __align__(16) __half g_ffh  [MM*1536];
__device__ __align__(16) __half g_qkvh [MM*1152];
__device__ __align__(16) __half g_kv3h [3][MM*768];

/* weights converted to half, once per launch */
__device__ __align__(16) __half g_wsa[6*1152*DD];
__device__ __align__(16) __half g_wso[6*DD*DD];
__device__ __align__(16) __half g_wca[6*1152*DD];
__device__ __align__(16) __half g_wco[6*DD*DD];
__device__ __align__(16) __half g_wf1[6*1536*DD];
__device__ __align__(16) __half g_wf2[6*DD*1536];

/* ------------------------------------------------------------------ */
/* fused weight conversion (all six tensors in one launch)             */
/* ------------------------------------------------------------------ */
#define C_WSA 663552   /* 6*1152*384/4 */
#define C_WSO 221184   /* 6*384*384/4  */
#define C_WF  884736   /* 6*1536*384/4 */
#define CVT_TOTAL (2*(C_WSA + C_WSO + C_WF))   /* float4 elements */
__global__ void cvtall_kernel(
    const float* __restrict__ sa_w, const float* __restrict__ sa_ow,
    const float* __restrict__ ca_w, const float* __restrict__ ca_ow,
    const float* __restrict__ f1w,  const float* __restrict__ f2w)
{
    long g = (long)blockIdx.x*256 + threadIdx.x;
    const float* s; __half* d; long o = g;
    if      (o < C_WSA)                       { s = sa_w;  d = g_wsa; }
    else if ((o -= C_WSA) < C_WSO)            { s = sa_ow; d = g_wso; }
    else if ((o -= C_WSO) < C_WSA)            { s = ca_w;  d = g_wca; }
    else if ((o -= C_WSA) < C_WSO)            { s = ca_ow; d = g_wco; }
    else if ((o -= C_WSO) < C_WF)             { s = f1w;   d = g_wf1; }
    else if ((o -= C_WF)  < C_WF)             { s = f2w;   d = g_wf2; }
    else return;
    float4 v = ((const float4*)s)[o];
    ((__half2*)d)[2*o]   = __floats2half2_rn(v.x, v.y);
    ((__half2*)d)[2*o+1] = __floats2half2_rn(v.z, v.w);
}

/* ------------------------------------------------------------------ */
/* 1) similarity (exact fp32 — protects top-k ordering)                */
/* ------------------------------------------------------------------ */
__global__ __launch_bounds__(128) void sim_kernel(
    const float* __restrict__ qt, const float* __restrict__ nd,
    float* __restrict__ sim)
{
    __shared__ float s_qt[SS*DD];
    __shared__ float s_nd[8][512];
    int b   = blockIdx.y;
    int n0  = blockIdx.x * 512;
    int tid = threadIdx.x;

    const float4* qtb = (const float4*)(qt + (long)b*SS*DD);
    for (int i = tid; i < SS*DD/4; i += 128)
        ((float4*)s_qt)[i] = qtb[i];

    float acc[14][4];
    #pragma unroll
    for (int h = 0; h < 14; h++)
        acc[h][0]=acc[h][1]=acc[h][2]=acc[h][3]=0.f;

    int lr = tid >> 1;
    int lk = (tid & 1) * 4;
    const float* ndb = nd + ((long)b*NN + n0)*DD;

    for (int k0 = 0; k0 < DD; k0 += 8) {
        __syncthreads();
        #pragma unroll
        for (int p = 0; p < 8; p++) {
            int r = p*64 + lr;
            float4 v = *(const float4*)(ndb + (long)r*DD + k0 + lk);
            s_nd[lk+0][r] = v.x; s_nd[lk+1][r] = v.y;
            s_nd[lk+2][r] = v.z; s_nd[lk+3][r] = v.w;
        }
        __syncthreads();
        #pragma unroll
        for (int k = 0; k < 8; k++) {
            float b0 = s_nd[k][tid];
            float b1 = s_nd[k][tid+128];
            float b2 = s_nd[k][tid+256];
            float b3 = s_nd[k][tid+384];
            #pragma unroll
            for (int h = 0; h < 14; h++) {
                float a = s_qt[h*DD + k0 + k];
                acc[h][0] = fmaf(a, b0, acc[h][0]);
                acc[h][1] = fmaf(a, b1, acc[h][1]);
                acc[h][2] = fmaf(a, b2, acc[h][2]);
                acc[h][3] = fmaf(a, b3, acc[h][3]);
            }
        }
    }
    #pragma unroll
    for (int h = 0; h < 14; h++) {
        float* srow = sim + ((long)(b*SS + h))*NN + n0;
        srow[tid]     = acc[h][0];
        srow[tid+128] = acc[h][1];
        srow[tid+256] = acc[h][2];
        srow[tid+384] = acc[h][3];
    }
}

/* ------------------------------------------------------------------ */
/* 2) top-k per (b,h) row                                              */
/* ------------------------------------------------------------------ */
__global__ __launch_bounds__(256) void topk_kernel(
    const float* __restrict__ sim, int* __restrict__ idx)
{
    __shared__ float sv[NN];
    __shared__ float rv[256];
    __shared__ int   ri[256];
    int row = blockIdx.x;
    int tid = threadIdx.x;
    const float* srow = sim + (long)row*NN;
    for (int j = tid; j < NN; j += 256) sv[j] = srow[j];
    __syncthreads();

    for (int it = 0; it < KN; it++) {
        float bv = -3.4e38f; int bi = 0;
        for (int j = tid; j < NN; j += 256) {
            float v = sv[j];
            if (v > bv) { bv = v; bi = j; }
        }
        rv[tid] = bv; ri[tid] = bi;
        __syncthreads();
        for (int s = 128; s > 0; s >>= 1) {
            if (tid < s) {
                float ov = rv[tid+s]; int oi = ri[tid+s];
                if (ov > rv[tid] || (ov == rv[tid] && oi < ri[tid])) {
                    rv[tid] = ov; ri[tid] = oi;
                }
            }
            __syncthreads();
        }
        if (tid == 0) {
            idx[row*KN + it] = ri[0];
            sv[ri[0]] = -3.4e38f;
        }
        __syncthreads();
    }
}

/* ------------------------------------------------------------------ */
/* 3) build: x0 f32 (broadcast qt), mem half (gathered nd rows)        */
/* ------------------------------------------------------------------ */
__global__ void build_kernel(
    const float* __restrict__ qt, const float* __restrict__ nd,
    const int* __restrict__ idx, float* __restrict__ x, __half* __restrict__ mem)
{
    int g = blockIdx.x*256 + threadIdx.x;
    int row = g / 96, c = g - row*96;
    int b  = row / (KN*SS);
    int rj = row - b*KN*SS;
    int j  = rj / SS, t = rj - j*SS;
    ((float4*)x)[g] = ((const float4*)qt)[(b*SS + t)*96 + c];
    int n = idx[(b*SS + t)*KN + j];
    float4 v = ((const float4*)nd)[((long)b*NN + n)*96 + c];
    ((__half2*)mem)[2*g]   = __floats2half2_rn(v.x, v.y);
    ((__half2*)mem)[2*g+1] = __floats2half2_rn(v.z, v.w);
}

/* ------------------------------------------------------------------ */
/* 4) LayerNorm: TWO rows per warp (doubled MLP, halved weight loads)  */
/*    MODE 0: f32 out   MODE 1: half out   MODE 2: f32 in-place + half */
/*    grid = MM/16 = 560 blocks of 256 threads                         */
/* ------------------------------------------------------------------ */
template<int MODE>
__global__ __launch_bounds__(256) void ln_kernel(
    const float* __restrict__ in, const float* __restrict__ w,
    const float* __restrict__ bias, void* __restrict__ outp,
    __half* __restrict__ outh2)
{
    int wid  = threadIdx.x >> 5;
    int lane = threadIdx.x & 31;
    int rowA = blockIdx.x*16 + wid*2;
    int rowB = rowA + 1;

    const float4* a4 = (const float4*)(in + (long)rowA*DD);
    const float4* b4r = (const float4*)(in + (long)rowB*DD);
    /* front-batched loads: 6 outstanding LDG.128 */
    float4 u0 = a4[lane],  u1 = a4[lane+32],  u2 = a4[lane+64];
    float4 t0 = b4r[lane], t1 = b4r[lane+32], t2 = b4r[lane+64];

    float sA = u0.x+u0.y+u0.z+u0.w + u1.x+u1.y+u1.z+u1.w + u2.x+u2.y+u2.z+u2.w;
    float sB = t0.x+t0.y+t0.z+t0.w + t1.x+t1.y+t1.z+t1.w + t2.x+t2.y+t2.z+t2.w;
    #pragma unroll
    for (int o = 16; o; o >>= 1) {
        sA += __shfl_xor_sync(0xffffffffu, sA, o);
        sB += __shfl_xor_sync(0xffffffffu, sB, o);
    }
    float muA = sA * (1.0f/DD);
    float muB = sB * (1.0f/DD);

    float d, dA = 0.f, dB = 0.f;
    d=u0.x-muA; dA=fmaf(d,d,dA); d=u0.y-muA; dA=fmaf(d,d,dA);
    d=u0.z-muA; dA=fmaf(d,d,dA); d=u0.w-muA; dA=fmaf(d,d,dA);
    d=u1.x-muA; dA=fmaf(d,d,dA); d=u1.y-muA; dA=fmaf(d,d,dA);
    d=u1.z-muA; dA=fmaf(d,d,dA); d=u1.w-muA; dA=fmaf(d,d,dA);
    d=u2.x-muA; dA=fmaf(d,d,dA); d=u2.y-muA; dA=fmaf(d,d,dA);
    d=u2.z-muA; dA=fmaf(d,d,dA); d=u2.w-muA; dA=fmaf(d,d,dA);
    d=t0.x-muB; dB=fmaf(d,d,dB); d=t0.y-muB; dB=fmaf(d,d,dB);
    d=t0.z-muB; dB=fmaf(d,d,dB); d=t0.w-muB; dB=fmaf(d,d,dB);
    d=t1.x-muB; dB=fmaf(d,d,dB); d=t1.y-muB; dB=fmaf(d,d,dB);
    d=t1.z-muB; dB=fmaf(d,d,dB); d=t1.w-muB; dB=fmaf(d,d,dB);
    d=t2.x-muB; dB=fmaf(d,d,dB); d=t2.y-muB; dB=fmaf(d,d,dB);
    d=t2.z-muB; dB=fmaf(d,d,dB); d=t2.w-muB; dB=fmaf(d,d,dB);
    #pragma unroll
    for (int o = 16; o; o >>= 1) {
        dA += __shfl_xor_sync(0xffffffffu, dA, o);
        dB += __shfl_xor_sync(0xffffffffu, dB, o);
    }
    float rA = rsqrtf(dA*(1.0f/DD) + 1e-5f);
    float rB = rsqrtf(dB*(1.0f/DD) + 1e-5f);

    const float4* w4 = (const float4*)w;
    const float4* b4 = (const float4*)bias;
    #pragma unroll
    for (int k = 0; k < 3; k++) {
        float4 vA = (k==0) ? u0 : (k==1) ? u1 : u2;
        float4 vB = (k==0) ? t0 : (k==1) ? t1 : t2;
        float4 wv = w4[lane + k*32], bv = b4[lane + k*32];   /* shared A/B */
        float ax = fmaf((vA.x-muA)*rA, wv.x, bv.x);
        float ay = fmaf((vA.y-muA)*rA, wv.y, bv.y);
        float az = fmaf((vA.z-muA)*rA, wv.z, bv.z);
        float aw = fmaf((vA.w-muA)*rA, wv.w, bv.w);
        float bx = fmaf((vB.x-muB)*rB, wv.x, bv.x);
        float by = fmaf((vB.y-muB)*rB, wv.y, bv.y);
        float bz = fmaf((vB.z-muB)*rB, wv.z, bv.z);
        float bw = fmaf((vB.w-muB)*rB, wv.w, bv.w);
        if (MODE == 1) {
            __half2* oA = (__half2*)outp + (long)rowA*(DD/2) + lane*2 + k*64;
            __half2* oB = (__half2*)outp + (long)rowB*(DD/2) + lane*2 + k*64;
            oA[0] = __floats2half2_rn(ax, ay); oA[1] = __floats2half2_rn(az, aw);
            oB[0] = __floats2half2_rn(bx, by); oB[1] = __floats2half2_rn(bz, bw);
        } else {
            float4* oA = (float4*)outp + (long)rowA*(DD/4) + lane + k*32;
            float4* oB = (float4*)outp + (long)rowB*(DD/4) + lane + k*32;
            *oA = make_float4(ax, ay, az, aw);
            *oB = make_float4(bx, by, bz, bw);
            if (MODE == 2) {
                __half2* hA = (__half2*)outh2 + (long)rowA*(DD/2) + lane*2 + k*64;
                __half2* hB = (__half2*)outh2 + (long)rowB*(DD/2) + lane*2 + k*64;
                hA[0] = __floats2half2_rn(ax, ay); hA[1] = __floats2half2_rn(az, aw);
                hB[0] = __floats2half2_rn(bx, by); hB[1] = __floats2half2_rn(bz, bw);
            }
        }
    }
}

/* ------------------------------------------------------------------ */
/* 5) fp16 mma.sync GEMM core, BK=32, 3-stage cp.async, ldmatrix.      */
/*    128x128x32 tile, 256 thr, warp 64x32, m16n8k16. 48KB static.     */
/* ------------------------------------------------------------------ */
#define LDSM4(d0,d1,d2,d3,a) \
    asm volatile("ldmatrix.sync.aligned.m8n8.x4.shared.b16 {%0,%1,%2,%3}, [%4];" \
        : "=r"(d0),"=r"(d1),"=r"(d2),"=r"(d3) : "r"(a))

#define CP16(dst, src) \
    asm volatile("cp.async.cg.shared.global [%0], [%1], 16;" \
        :: "r"(dst), "l"(src))
#define CP_COMMIT() asm volatile("cp.async.commit_group;")
#define CP_WAIT1()  asm volatile("cp.async.wait_group 1;")

__device__ __forceinline__ void mma_f16(
    float* c, const uint32_t* a, uint32_t b0, uint32_t b1)
{
    asm volatile(
        "mma.sync.aligned.m16n8k16.row.col.f32.f16.f16.f32 "
        "{%0,%1,%2,%3}, {%4,%5,%6,%7}, {%8,%9}, {%0,%1,%2,%3};"
        : "+f"(c[0]), "+f"(c[1]), "+f"(c[2]), "+f"(c[3])
        : "r"(a[0]), "r"(a[1]), "r"(a[2]), "r"(a[3]), "r"(b0), "r"(b1));
}

template<int DO_GELU, int DO_RES, int OUT_HALF>
__device__ __forceinline__ void gemm_core(
    const __half* __restrict__ A, const __half* __restrict__ B,
    const float* __restrict__ bias, const float* __restrict__ res,
    void* __restrict__ Cout, int N, int K, int m0, int n0)
{
    __shared__ __align__(128) uint4 As4[3][512];   /* 3 stages x 8KB */
    __shared__ __align__(128) uint4 Bs4[3][512];

    int tid = threadIdx.x, lane = tid & 31, wid = tid >> 5;
    int wm = wid >> 2, wn = wid & 3;
    int gid = lane >> 2, tig = lane & 3;

    int r  = tid >> 1;
    int cp = (tid & 1) * 2;
    const __half* ap = A + (long)(m0 + r)*K + cp*8;
    const __half* bp = B + (long)(n0 + r)*K + cp*8;
    int sw  = (r >> 1) & 3;
    int sA0 = r*4 + (cp ^ sw), sA1 = r*4 + ((cp+1) ^ sw);
    uint32_t dA0 = (uint32_t)__cvta_generic_to_shared(&As4[0][sA0]);
    uint32_t dA1 = (uint32_t)__cvta_generic_to_shared(&As4[0][sA1]);
    uint32_t dB0 = (uint32_t)__cvta_generic_to_shared(&Bs4[0][sA0]);
    uint32_t dB1 = (uint32_t)__cvta_generic_to_shared(&Bs4[0][sA1]);

    uint32_t a_addr[4], b_addr[2];
    {
        int rr = (lane & 15), ch = (lane >> 4);
        #pragma unroll
        for (int mt = 0; mt < 4; mt++) {
            int row = wm*64 + mt*16 + rr;
            a_addr[mt] = (uint32_t)__cvta_generic_to_shared(
                &As4[0][row*4 + (ch ^ ((row>>1)&3))]);
        }
        #pragma unroll
        for (int nt2 = 0; nt2 < 2; nt2++) {
            int row = wn*32 + nt2*16 + rr;
            b_addr[nt2] = (uint32_t)__cvta_generic_to_shared(
                &Bs4[0][row*4 + (ch ^ ((row>>1)&3))]);
        }
    }

    float acc[4][4][4];
    #pragma unroll
    for (int i = 0; i < 4; i++)
        #pragma unroll
        for (int j = 0; j < 4; j++)
            acc[i][j][0]=acc[i][j][1]=acc[i][j][2]=acc[i][j][3]=0.f;

    int nit = K >> 5;
    {
        CP16(dA0, ap);            CP16(dA1, ap + 8);
        CP16(dB0, bp);            CP16(dB1, bp + 8);
        CP_COMMIT();
        CP16(dA0 + 8192, ap + 32); CP16(dA1 + 8192, ap + 40);
        CP16(dB0 + 8192, bp + 32); CP16(dB1 + 8192, bp + 40);
        CP_COMMIT();
    }

    int st = 0, stw = 2;
    for (int it = 0; it < nit; it++) {
        CP_WAIT1();
        __syncthreads();
        if (it + 2 < nit) {
            const __half* an = ap + (it+2)*32;
            const __half* bn = bp + (it+2)*32;
            uint32_t so = (uint32_t)(stw * 8192);
            CP16(dA0 + so, an); CP16(dA1 + so, an + 8);
            CP16(dB0 + so, bn); CP16(dB1 + so, bn + 8);
        }
        CP_COMMIT();

        uint32_t coff = (uint32_t)(st * 8192);
        #pragma unroll
        for (int ks = 0; ks < 2; ks++) {
            uint32_t kb = (uint32_t)(ks * 32);
            uint32_t af[4][4], bf[4][2];
            #pragma unroll
            for (int mt = 0; mt < 4; mt++)
                LDSM4(af[mt][0], af[mt][1], af[mt][2], af[mt][3],
                      (a_addr[mt] + coff) ^ kb);
            #pragma unroll
            for (int nt2 = 0; nt2 < 2; nt2++) {
                uint32_t r0,r1,r2,r3;
                LDSM4(r0, r1, r2, r3, (b_addr[nt2] + coff) ^ kb);
                bf[nt2*2+0][0] = r0; bf[nt2*2+0][1] = r2;
                bf[nt2*2+1][0] = r1; bf[nt2*2+1][1] = r3;
            }
            #pragma unroll
            for (int mt = 0; mt < 4; mt++)
                #pragma unroll
                for (int nt = 0; nt < 4; nt++)
                    mma_f16(acc[mt][nt], af[mt], bf[nt][0], bf[nt][1]);
        }
        st  = (st  == 2) ? 0 : st  + 1;
        stw = (stw == 2) ? 0 : stw + 1;
    }

    /* epilogue */
    #pragma unroll
    for (int mt = 0; mt < 4; mt++) {
        int r0r = m0 + wm*64 + mt*16 + gid;
        #pragma unroll
        for (int nt = 0; nt < 4; nt++) {
            int cb = n0 + wn*32 + nt*8 + tig*2;
            float bb0 = bias[cb], bb1 = bias[cb+1];
            float v00 = acc[mt][nt][0] + bb0, v01 = acc[mt][nt][1] + bb1;
            float v10 = acc[mt][nt][2] + bb0, v11 = acc[mt][nt][3] + bb1;
            if (DO_GELU) {
                v00 = 0.5f*v00*(1.0f + erff(v00*0.70710678118654752f));
                v01 = 0.5f*v01*(1.0f + erff(v01*0.70710678118654752f));
                v10 = 0.5f*v10*(1.0f + erff(v10*0.70710678118654752f));
                v11 = 0.5f*v11*(1.0f + erff(v11*0.70710678118654752f));
            }
            long o0 = (long)r0r*N + cb;
            long o1 = (long)(r0r+8)*N + cb;
            if (DO_RES) {
                float2 q0 = *(const float2*)(res + o0);
                float2 q1 = *(const float2*)(res + o1);
                v00 += q0.x; v01 += q0.y; v10 += q1.x; v11 += q1.y;
            }
            if (OUT_HALF) {
                __half2* Ch = (__half2*)Cout;
                Ch[o0 >> 1] = __floats2half2_rn(v00, v01);
                Ch[o1 >> 1] = __floats2half2_rn(v10, v11);
            } else {
                float* Cf = (float*)Cout;
                *(float2*)(Cf + o0) = make_float2(v00, v01);
                *(float2*)(Cf + o1) = make_float2(v10, v11);
            }
        }
    }
}

template<int DO_GELU, int DO_RES, int OUT_HALF>
__global__ __launch_bounds__(256,2) void hgemm(
    const __half* __restrict__ A, const __half* __restrict__ B,
    const float* __restrict__ bias, const float* __restrict__ res,
    void* __restrict__ Cout, int N, int K)
{
    gemm_core<DO_GELU,DO_RES,OUT_HALF>(A, B, bias, res, Cout, N, K,
                                       blockIdx.y << 7, blockIdx.x << 7);
}

/* batched kv projections for 3 layers (half output): 1260 blocks.     */
__global__ __launch_bounds__(256,2) void hgemm_kv(
    const __half* __restrict__ memory,
    const __half* __restrict__ wca_all,
    const float* __restrict__ ca_b,
    __half* __restrict__ kv3,
    int l0)
{
    int bx = blockIdx.x;
    int l  = bx / 420, rr = bx - l*420;
    int n0 = (rr % 6) << 7, m0 = (rr / 6) << 7;
    const __half* B   = wca_all + (long)(l0+l)*1152*DD + (long)384*DD;
    const float*  bb  = ca_b + (l0+l)*1152 + 384;
    __half* C = kv3 + (long)l*MM*768;
    gemm_core<0,0,1>(memory, B, bb, (const float*)0, C, 768, DD, m0, n0);
}

/* ------------------------------------------------------------------ */
/* 6) attention: 4 warps/block, one (seq,head) per warp; half in/out.  */
/* ------------------------------------------------------------------ */
__global__ __launch_bounds__(128) void attn_kernel(
    const __half* __restrict__ qp, int qld,
    const __half* __restrict__ kp, int kld,
    const __half* __restrict__ vp, int vld,
    __half* __restrict__ op)
{
    __shared__ __align__(16) float sq [4][SS*HDD];
    __shared__ __align__(16) float sk [4][SS*HDD];
    __shared__ __align__(16) float svv[4][SS*HDD];
    __shared__ float sc[4][SS*16];
    int w    = threadIdx.x >> 5;
    int lane = threadIdx.x & 31;
    int pair = blockIdx.x*4 + w;
    int seq  = pair >> 3, h = pair & 7;
    int base = seq*SS;
    int hoff = h*HDD;

    for (int i2 = lane; i2 < SS*HDD/2; i2 += 32) {
        int e2 = i2*2;
        int t = e2 / HDD, e = e2 - t*HDD;
        float2 fq = __half22float2(*(const __half2*)(qp + (long)(base+t)*qld + hoff + e));
        float2 fk = __half22float2(*(const __half2*)(kp + (long)(base+t)*kld + hoff + e));
        float2 fv = __half22float2(*(const __half2*)(vp + (long)(base+t)*vld + hoff + e));
        sq [w][t*HDD+e] = fq.x; sq [w][t*HDD+e+1] = fq.y;
        sk [w][t*HDD+e] = fk.x; sk [w][t*HDD+e+1] = fk.y;
        svv[w][t*HDD+e] = fv.x; svv[w][t*HDD+e+1] = fv.y;
    }
    __syncwarp();

    const float scale = 0.14433756729740644f;   /* 1/sqrt(48) */
    for (int i = lane; i < SS*SS; i += 32) {
        int t = i / SS, u = i - t*SS;
        const float4* a4 = (const float4*)(sq[w] + t*HDD);
        const float4* b4 = (const float4*)(sk[w] + u*HDD);
        float s = 0.f;
        #pragma unroll
        for (int g = 0; g < 12; g++) {
            float4 a = a4[g], b = b4[g];
            s = fmaf(a.x,b.x,s); s = fmaf(a.y,b.y,s);
            s = fmaf(a.z,b.z,s); s = fmaf(a.w,b.w,s);
        }
        sc[w][t*16 + u] = s * scale;
    }
    __syncwarp();

    if (lane < SS) {
        float m = -3.4e38f;
        #pragma unroll
        for (int u = 0; u < SS; u++) m = fmaxf(m, sc[w][lane*16+u]);
        float sum = 0.f;
        #pragma unroll
        for (int u = 0; u < SS; u++) {
            float e = expf(sc[w][lane*16+u] - m);
            sc[w][lane*16+u] = e; sum += e;
        }
        float inv = 1.0f/sum;
        #pragma unroll
        for (int u = 0; u < SS; u++) sc[w][lane*16+u] *= inv;
    }
    __syncwarp();

    for (int i = lane; i < SS*HDD; i += 32) {
        int t = i / HDD, e = i - t*HDD;
        float o = 0.f;
        #pragma unroll
        for (int u = 0; u < SS; u++)
            o = fmaf(sc[w][t*16+u], svv[w][u*HDD+e], o);
        op[(long)(base+t)*DD + hoff + e] = __float2half(o);
    }
}

/* ------------------------------------------------------------------ */
/* host orchestration (fork/join streams for independent work)         */
/* ------------------------------------------------------------------ */
extern "C" void kernel_launch(void* const* d_in, const int* in_sizes, int n_in,
                              void* d_out, int out_size)
{
    const float* qt    = (const float*)d_in[0];
    const float* nd    = (const float*)d_in[1];
    const float* sa_w  = (const float*)d_in[2];
    const float* sa_b  = (const float*)d_in[3];
    const float* sa_ow = (const float*)d_in[4];
    const float* sa_ob = (const float*)d_in[5];
    const float* ca_w  = (const float*)d_in[6];
    const float* ca_b  = (const float*)d_in[7];
    const float* ca_ow = (const float*)d_in[8];
    const float* ca_ob = (const float*)d_in[9];
    const float* ln1w  = (const float*)d_in[10];
    const float* ln1b  = (const float*)d_in[11];
    const float* ln2w  = (const float*)d_in[12];
    const float* ln2b  = (const float*)d_in[13];
    const float* ln3w  = (const float*)d_in[14];
    const float* ln3b  = (const float*)d_in[15];
    const float* f1w   = (const float*)d_in[16];
    const float* f1b   = (const float*)d_in[17];
    const float* f2w   = (const float*)d_in[18];
    const float* f2b   = (const float*)d_in[19];
    const float* fnw   = (const float*)d_in[20];
    const float* fnb   = (const float*)d_in[21];
    float* out = (float*)d_out;

    float *sim,*x; int* idx;
    __half *hh,*aoh,*qh,*memh,*mem2h,*ffh,*qkvh,*kv3h;
    __half *wsa,*wso,*wca,*wco,*wf1,*wf2;
    cudaGetSymbolAddress((void**)&sim,   g_sim);
    cudaGetSymbolAddress((void**)&idx,   g_idx);
    cudaGetSymbolAddress((void**)&x,     g_x);
    cudaGetSymbolAddress((void**)&hh,    g_hh);
    cudaGetSymbolAddress((void**)&aoh,   g_aoh);
    cudaGetSymbolAddress((void**)&qh,    g_qh);
    cudaGetSymbolAddress((void**)&memh,  g_memh);
    cudaGetSymbolAddress((void**)&mem2h, g_mem2h);
    cudaGetSymbolAddress((void**)&ffh,   g_ffh);
    cudaGetSymbolAddress((void**)&qkvh,  g_qkvh);
    cudaGetSymbolAddress((void**)&kv3h,  g_kv3h);
    cudaGetSymbolAddress((void**)&wsa,   g_wsa);
    cudaGetSymbolAddress((void**)&wso,   g_wso);
    cudaGetSymbolAddress((void**)&wca,   g_wca);
    cudaGetSymbolAddress((void**)&wco,   g_wco);
    cudaGetSymbolAddress((void**)&wf1,   g_wf1);
    cudaGetSymbolAddress((void**)&wf2,   g_wf2);

    /* side streams + fork/join events (host-side only; not on replay path) */
    cudaStream_t s1, s2;
    cudaStreamCreateWithFlags(&s1, cudaStreamNonBlocking);
    cudaStreamCreateWithFlags(&s2, cudaStreamNonBlocking);
    cudaEvent_t evFork, evCvt, evBuild, evKV0, evSnap, evKV3;
    cudaEventCreateWithFlags(&evFork,  cudaEventDisableTiming);
    cudaEventCreateWithFlags(&evCvt,   cudaEventDisableTiming);
    cudaEventCreateWithFlags(&evBuild, cudaEventDisableTiming);
    cudaEventCreateWithFlags(&evKV0,   cudaEventDisableTiming);
    cudaEventCreateWithFlags(&evSnap,  cudaEventDisableTiming);
    cudaEventCreateWithFlags(&evKV3,   cudaEventDisableTiming);

    /* fork: weight conversion runs on s1, overlapped with retrieval */
    cudaEventRecord(evFork, 0);
    cudaStreamWaitEvent(s1, evFork, 0);
    cvtall_kernel<<<(CVT_TOTAL + 255)/256, 256, 0, s1>>>(
        sa_w, sa_ow, ca_w, ca_ow, f1w, f2w);
    cudaEventRecord(evCvt, s1);

    /* stage A: retrieval (default stream) */
    sim_kernel  <<<dim3(16,64), 128>>>(qt, nd, sim);
    topk_kernel <<<BB*SS, 256>>>(sim, idx);
    build_kernel<<<3360, 256>>>(qt, nd, idx, x, memh);
    cudaEventRecord(evBuild, 0);

    /* s2: kv projections layers 0-2 (needs memh + converted wca) */
    cudaStreamWaitEvent(s2, evBuild, 0);
    cudaStreamWaitEvent(s2, evCvt, 0);
    hgemm_kv<<<1260, 256, 0, s2>>>(memh, wca, ca_b, kv3h, 0);
    cudaEventRecord(evKV0, s2);

    /* default stream needs converted weights before first hgemm */
    cudaStreamWaitEvent(0, evCvt, 0);

    /* stage B: 6 decoder blocks */
    for (int i = 0; i < 6; i++) {
        __half* kvl = kv3h + (long)(i % 3)*MM*768;

        /* self-attention */
        ln_kernel<1><<<560,256>>>(x, ln1w + i*DD, ln1b + i*DD, hh, (__half*)0);
        hgemm<0,0,1><<<dim3(9,70),256>>>(hh, wsa + (long)i*1152*DD,
                                         sa_b + i*1152, (const float*)0,
                                         qkvh, 1152, DD);
        attn_kernel<<<1280,128>>>(qkvh,1152, qkvh+384,1152, qkvh+768,1152, aoh);
        hgemm<0,1,0><<<dim3(3,70),256>>>(aoh, wso + (long)i*DD*DD,
                                         sa_ob + i*DD, x, x, DD, DD);

        /* cross-attention: q projection (kv computed on s2) */
        ln_kernel<1><<<560,256>>>(x, ln2w + i*DD, ln2b + i*DD, hh, (__half*)0);
        hgemm<0,0,1><<<dim3(3,70),256>>>(hh, wca + (long)i*1152*DD,
                                         ca_b + i*1152, (const float*)0,
                                         qh, DD, DD);
        if (i == 0) cudaStreamWaitEvent(0, evKV0, 0);   /* join kv 0-2 */
        if (i == 3) cudaStreamWaitEvent(0, evKV3, 0);   /* join kv 3-5 */
        attn_kernel<<<1280,128>>>(qh,384, kvl,768, kvl+384,768, aoh);
        hgemm<0,1,0><<<dim3(3,70),256>>>(aoh, wco + (long)i*DD*DD,
                                         ca_ob + i*DD, x, x, DD, DD);

        /* FFN */
        ln_kernel<1><<<560,256>>>(x, ln3w + i*DD, ln3b + i*DD, hh, (__half*)0);
        hgemm<1,0,1><<<dim3(12,70),256>>>(hh, wf1 + (long)i*1536*DD,
                                          f1b + i*1536, (const float*)0,
                                          ffh, 1536, DD);
        hgemm<0,1,0><<<dim3(3,70),256>>>(ffh, wf2 + (long)i*DD*1536,
                                         f2b + i*DD, x, x, DD, 1536);

        /* mid-stack snapshot; kv projections for layers 3-5 fork to s2 */
        if (i == 2) {
            ln_kernel<2><<<560,256>>>(x, fnw, fnb, x, mem2h);
            cudaEventRecord(evSnap, 0);
            cudaStreamWaitEvent(s2, evSnap, 0);
            hgemm_kv<<<1260, 256, 0, s2>>>(mem2h, wca, ca_b, kv3h, 3);
            cudaEventRecord(evKV3, s2);
        }
    }

    /* final norm straight into d_out (f32) */
    ln_kernel<0><<<560,256>>>(x, fnw + DD, fnb + DD, out, (__half*)0);

    cudaEventDestroy(evFork);  cudaEventDestroy(evCvt);
    cudaEventDestroy(evBuild); cudaEventDestroy(evKV0);
    cudaEventDestroy(evSnap);  cudaEventDestroy(evKV3);
    cudaStreamDestroy(s1);
    cudaStreamDestroy(s2);
}

// round 17
// speedup vs baseline: 1.0267x; 1.0119x over previous
#include <cuda_runtime.h>
#include <cuda_fp16.h>
#include <cstdint>
#include <math.h>

#define BB 64
#define NN 8192
#define SS 14
#define KN 10
#define DD 384
#define NSEQ (BB*KN)      /* 640  */
#define MM (NSEQ*SS)      /* 8960 */
#define NHH 8
#define HDD 48

/* ------------------------------------------------------------------ */
/* scratch (device globals: no allocation allowed)                     */
/* ------------------------------------------------------------------ */
__device__ float g_sim[BB*SS*NN];
__device__ int   g_idx[BB*SS*KN];
__device__ float g_x  [MM*DD];

__device__ __align__(16) __half g_hh   [MM*DD];
__device__ __align__(16) __half g_aoh  [MM*DD];
__device__ __align__(16) __half g_qh   [MM*DD];
__device__ __align__(16) __half g_memh [MM*DD];
__device__ __align__(16) __half g_mem2h[MM*DD];
__device__ __align__(16) __half g_ffh  [MM*1536];
__device__ __align__(16) __half g_qkvh [MM*1152];
__device__ __align__(16) __half g_kv3h [3][MM*768];

/* weights converted to half, once per launch */
__device__ __align__(16) __half g_wsa[6*1152*DD];
__device__ __align__(16) __half g_wso[6*DD*DD];
__device__ __align__(16) __half g_wca[6*1152*DD];
__device__ __align__(16) __half g_wco[6*DD*DD];
__device__ __align__(16) __half g_wf1[6*1536*DD];
__device__ __align__(16) __half g_wf2[6*DD*1536];

/* ------------------------------------------------------------------ */
/* fused weight conversion (all six tensors in one launch)             */
/* ------------------------------------------------------------------ */
#define C_WSA 663552   /* 6*1152*384/4 */
#define C_WSO 221184   /* 6*384*384/4  */
#define C_WF  884736   /* 6*1536*384/4 */
#define CVT_TOTAL (2*(C_WSA + C_WSO + C_WF))   /* float4 elements */
__global__ void cvtall_kernel(
    const float* __restrict__ sa_w, const float* __restrict__ sa_ow,
    const float* __restrict__ ca_w, const float* __restrict__ ca_ow,
    const float* __restrict__ f1w,  const float* __restrict__ f2w)
{
    long g = (long)blockIdx.x*256 + threadIdx.x;
    const float* s; __half* d; long o = g;
    if      (o < C_WSA)                       { s = sa_w;  d = g_wsa; }
    else if ((o -= C_WSA) < C_WSO)            { s = sa_ow; d = g_wso; }
    else if ((o -= C_WSO) < C_WSA)            { s = ca_w;  d = g_wca; }
    else if ((o -= C_WSA) < C_WSO)            { s = ca_ow; d = g_wco; }
    else if ((o -= C_WSO) < C_WF)             { s = f1w;   d = g_wf1; }
    else if ((o -= C_WF)  < C_WF)             { s = f2w;   d = g_wf2; }
    else return;
    float4 v = ((const float4*)s)[o];
    ((__half2*)d)[2*o]   = __floats2half2_rn(v.x, v.y);
    ((__half2*)d)[2*o+1] = __floats2half2_rn(v.z, v.w);
}

/* ------------------------------------------------------------------ */
/* packed dual-fp32 FMA (Blackwell f32x2; each lane exact IEEE fma)    */
/* ------------------------------------------------------------------ */
__device__ __forceinline__ void ffma2(
    unsigned long long& c, unsigned long long a, unsigned long long b)
{
    asm("fma.rn.f32x2 %0, %1, %2, %0;" : "+l"(c) : "l"(a), "l"(b));
}
__device__ __forceinline__ unsigned long long pack2(float lo, float hi)
{
    unsigned long long r;
    asm("mov.b64 %0, {%1, %2};" : "=l"(r) : "f"(lo), "f"(hi));
    return r;
}

/* ------------------------------------------------------------------ */
/* 1) similarity (exact fp32; h-pair packed FFMA2 inner loop)          */
/* ------------------------------------------------------------------ */
__global__ __launch_bounds__(128) void sim_kernel(
    const float* __restrict__ qt, const float* __restrict__ nd,
    float* __restrict__ sim)
{
    /* s_qtT[k][hp] = (qt[2hp][k], qt[2hp+1][k]); scalar view k*14 + h */
    __shared__ float s_qtT[DD*SS];     /* 21.5 KB */
    __shared__ float s_nd[8][512];     /* 16 KB, [k][n] */
    int b   = blockIdx.y;
    int n0  = blockIdx.x * 512;
    int tid = threadIdx.x;

    const float* qtb = qt + (long)b*SS*DD;
    for (int i = tid; i < SS*DD; i += 128) {
        int h = i / DD, k = i - h*DD;        /* coalesced gmem read */
        s_qtT[k*SS + h] = qtb[i];
    }

    unsigned long long acc[7][4];
    #pragma unroll
    for (int hp = 0; hp < 7; hp++)
        #pragma unroll
        for (int j = 0; j < 4; j++) acc[hp][j] = 0ull;

    int lr = tid >> 1;
    int lk = (tid & 1) * 4;
    const float* ndb = nd + ((long)b*NN + n0)*DD;

    for (int k0 = 0; k0 < DD; k0 += 8) {
        __syncthreads();
        #pragma unroll
        for (int p = 0; p < 8; p++) {
            int r = p*64 + lr;
            float4 v = *(const float4*)(ndb + (long)r*DD + k0 + lk);
            s_nd[lk+0][r] = v.x; s_nd[lk+1][r] = v.y;
            s_nd[lk+2][r] = v.z; s_nd[lk+3][r] = v.w;
        }
        __syncthreads();
        #pragma unroll
        for (int k = 0; k < 8; k++) {
            unsigned long long B0 = pack2(s_nd[k][tid],     s_nd[k][tid]);
            unsigned long long B1 = pack2(s_nd[k][tid+128], s_nd[k][tid+128]);
            unsigned long long B2 = pack2(s_nd[k][tid+256], s_nd[k][tid+256]);
            unsigned long long B3 = pack2(s_nd[k][tid+384], s_nd[k][tid+384]);
            const float2* arow = (const float2*)(s_qtT + (k0 + k)*SS);
            #pragma unroll
            for (int hp = 0; hp < 7; hp++) {
                float2 ap = arow[hp];                  /* ld.shared.b64 */
                unsigned long long A2 = pack2(ap.x, ap.y);
                ffma2(acc[hp][0], A2, B0);
                ffma2(acc[hp][1], A2, B1);
                ffma2(acc[hp][2], A2, B2);
                ffma2(acc[hp][3], A2, B3);
            }
        }
    }
    #pragma unroll
    for (int hp = 0; hp < 7; hp++) {
        #pragma unroll
        for (int j = 0; j < 4; j++) {
            float lo, hi;
            asm("mov.b64 {%0, %1}, %2;" : "=f"(lo), "=f"(hi) : "l"(acc[hp][j]));
            sim[((long)(b*SS + 2*hp  ))*NN + n0 + tid + j*128] = lo;
            sim[((long)(b*SS + 2*hp+1))*NN + n0 + tid + j*128] = hi;
        }
    }
}

/* ------------------------------------------------------------------ */
/* 2) top-k per (b,h) row                                              */
/* ------------------------------------------------------------------ */
__global__ __launch_bounds__(256) void topk_kernel(
    const float* __restrict__ sim, int* __restrict__ idx)
{
    __shared__ float sv[NN];
    __shared__ float rv[256];
    __shared__ int   ri[256];
    int row = blockIdx.x;
    int tid = threadIdx.x;
    const float* srow = sim + (long)row*NN;
    for (int j = tid; j < NN; j += 256) sv[j] = srow[j];
    __syncthreads();

    for (int it = 0; it < KN; it++) {
        float bv = -3.4e38f; int bi = 0;
        for (int j = tid; j < NN; j += 256) {
            float v = sv[j];
            if (v > bv) { bv = v; bi = j; }
        }
        rv[tid] = bv; ri[tid] = bi;
        __syncthreads();
        for (int s = 128; s > 0; s >>= 1) {
            if (tid < s) {
                float ov = rv[tid+s]; int oi = ri[tid+s];
                if (ov > rv[tid] || (ov == rv[tid] && oi < ri[tid])) {
                    rv[tid] = ov; ri[tid] = oi;
                }
            }
            __syncthreads();
        }
        if (tid == 0) {
            idx[row*KN + it] = ri[0];
            sv[ri[0]] = -3.4e38f;
        }
        __syncthreads();
    }
}

/* ------------------------------------------------------------------ */
/* 3) build: x0 f32 (broadcast qt), mem half (gathered nd rows)        */
/* ------------------------------------------------------------------ */
__global__ void build_kernel(
    const float* __restrict__ qt, const float* __restrict__ nd,
    const int* __restrict__ idx, float* __restrict__ x, __half* __restrict__ mem)
{
    int g = blockIdx.x*256 + threadIdx.x;
    int row = g / 96, c = g - row*96;
    int b  = row / (KN*SS);
    int rj = row - b*KN*SS;
    int j  = rj / SS, t = rj - j*SS;
    ((float4*)x)[g] = ((const float4*)qt)[(b*SS + t)*96 + c];
    int n = idx[(b*SS + t)*KN + j];
    float4 v = ((const float4*)nd)[((long)b*NN + n)*96 + c];
    ((__half2*)mem)[2*g]   = __floats2half2_rn(v.x, v.y);
    ((__half2*)mem)[2*g+1] = __floats2half2_rn(v.z, v.w);
}

/* ------------------------------------------------------------------ */
/* 4) LayerNorm: TWO rows per warp.                                    */
/*    MODE 0: f32 out   MODE 1: half out   MODE 2: f32 in-place + half */
/* ------------------------------------------------------------------ */
template<int MODE>
__global__ __launch_bounds__(256) void ln_kernel(
    const float* __restrict__ in, const float* __restrict__ w,
    const float* __restrict__ bias, void* __restrict__ outp,
    __half* __restrict__ outh2)
{
    int wid  = threadIdx.x >> 5;
    int lane = threadIdx.x & 31;
    int rowA = blockIdx.x*16 + wid*2;
    int rowB = rowA + 1;

    const float4* a4 = (const float4*)(in + (long)rowA*DD);
    const float4* b4r = (const float4*)(in + (long)rowB*DD);
    float4 u0 = a4[lane],  u1 = a4[lane+32],  u2 = a4[lane+64];
    float4 t0 = b4r[lane], t1 = b4r[lane+32], t2 = b4r[lane+64];

    float sA = u0.x+u0.y+u0.z+u0.w + u1.x+u1.y+u1.z+u1.w + u2.x+u2.y+u2.z+u2.w;
    float sB = t0.x+t0.y+t0.z+t0.w + t1.x+t1.y+t1.z+t1.w + t2.x+t2.y+t2.z+t2.w;
    #pragma unroll
    for (int o = 16; o; o >>= 1) {
        sA += __shfl_xor_sync(0xffffffffu, sA, o);
        sB += __shfl_xor_sync(0xffffffffu, sB, o);
    }
    float muA = sA * (1.0f/DD);
    float muB = sB * (1.0f/DD);

    float d, dA = 0.f, dB = 0.f;
    d=u0.x-muA; dA=fmaf(d,d,dA); d=u0.y-muA; dA=fmaf(d,d,dA);
    d=u0.z-muA; dA=fmaf(d,d,dA); d=u0.w-muA; dA=fmaf(d,d,dA);
    d=u1.x-muA; dA=fmaf(d,d,dA); d=u1.y-muA; dA=fmaf(d,d,dA);
    d=u1.z-muA; dA=fmaf(d,d,dA); d=u1.w-muA; dA=fmaf(d,d,dA);
    d=u2.x-muA; dA=fmaf(d,d,dA); d=u2.y-muA; dA=fmaf(d,d,dA);
    d=u2.z-muA; dA=fmaf(d,d,dA); d=u2.w-muA; dA=fmaf(d,d,dA);
    d=t0.x-muB; dB=fmaf(d,d,dB); d=t0.y-muB; dB=fmaf(d,d,dB);
    d=t0.z-muB; dB=fmaf(d,d,dB); d=t0.w-muB; dB=fmaf(d,d,dB);
    d=t1.x-muB; dB=fmaf(d,d,dB); d=t1.y-muB; dB=fmaf(d,d,dB);
    d=t1.z-muB; dB=fmaf(d,d,dB); d=t1.w-muB; dB=fmaf(d,d,dB);
    d=t2.x-muB; dB=fmaf(d,d,dB); d=t2.y-muB; dB=fmaf(d,d,dB);
    d=t2.z-muB; dB=fmaf(d,d,dB); d=t2.w-muB; dB=fmaf(d,d,dB);
    #pragma unroll
    for (int o = 16; o; o >>= 1) {
        dA += __shfl_xor_sync(0xffffffffu, dA, o);
        dB += __shfl_xor_sync(0xffffffffu, dB, o);
    }
    float rA = rsqrtf(dA*(1.0f/DD) + 1e-5f);
    float rB = rsqrtf(dB*(1.0f/DD) + 1e-5f);

    const float4* w4 = (const float4*)w;
    const float4* b4 = (const float4*)bias;
    #pragma unroll
    for (int k = 0; k < 3; k++) {
        float4 vA = (k==0) ? u0 : (k==1) ? u1 : u2;
        float4 vB = (k==0) ? t0 : (k==1) ? t1 : t2;
        float4 wv = w4[lane + k*32], bv = b4[lane + k*32];
        float ax = fmaf((vA.x-muA)*rA, wv.x, bv.x);
        float ay = fmaf((vA.y-muA)*rA, wv.y, bv.y);
        float az = fmaf((vA.z-muA)*rA, wv.z, bv.z);
        float aw = fmaf((vA.w-muA)*rA, wv.w, bv.w);
        float bx = fmaf((vB.x-muB)*rB, wv.x, bv.x);
        float by = fmaf((vB.y-muB)*rB, wv.y, bv.y);
        float bz = fmaf((vB.z-muB)*rB, wv.z, bv.z);
        float bw = fmaf((vB.w-muB)*rB, wv.w, bv.w);
        if (MODE == 1) {
            __half2* oA = (__half2*)outp + (long)rowA*(DD/2) + lane*2 + k*64;
            __half2* oB = (__half2*)outp + (long)rowB*(DD/2) + lane*2 + k*64;
            oA[0] = __floats2half2_rn(ax, ay); oA[1] = __floats2half2_rn(az, aw);
            oB[0] = __floats2half2_rn(bx, by); oB[1] = __floats2half2_rn(bz, bw);
        } else {
            float4* oA = (float4*)outp + (long)rowA*(DD/4) + lane + k*32;
            float4* oB = (float4*)outp + (long)rowB*(DD/4) + lane + k*32;
            *oA = make_float4(ax, ay, az, aw);
            *oB = make_float4(bx, by, bz, bw);
            if (MODE == 2) {
                __half2* hA = (__half2*)outh2 + (long)rowA*(DD/2) + lane*2 + k*64;
                __half2* hB = (__half2*)outh2 + (long)rowB*(DD/2) + lane*2 + k*64;
                hA[0] = __floats2half2_rn(ax, ay); hA[1] = __floats2half2_rn(az, aw);
                hB[0] = __floats2half2_rn(bx, by); hB[1] = __floats2half2_rn(bz, bw);
            }
        }
    }
}

/* ------------------------------------------------------------------ */
/* 5) fp16 mma.sync GEMM core, BK=32, 3-stage cp.async, ldmatrix.      */
/*    128x128x32 tile, 256 thr, warp 64x32, m16n8k16. 48KB static.     */
/* ------------------------------------------------------------------ */
#define LDSM4(d0,d1,d2,d3,a) \
    asm volatile("ldmatrix.sync.aligned.m8n8.x4.shared.b16 {%0,%1,%2,%3}, [%4];" \
        : "=r"(d0),"=r"(d1),"=r"(d2),"=r"(d3) : "r"(a))

#define CP16(dst, src) \
    asm volatile("cp.async.cg.shared.global [%0], [%1], 16;" \
        :: "r"(dst), "l"(src))
#define CP_COMMIT() asm volatile("cp.async.commit_group;")
#define CP_WAIT1()  asm volatile("cp.async.wait_group 1;")

__device__ __forceinline__ void mma_f16(
    float* c, const uint32_t* a, uint32_t b0, uint32_t b1)
{
    asm volatile(
        "mma.sync.aligned.m16n8k16.row.col.f32.f16.f16.f32 "
        "{%0,%1,%2,%3}, {%4,%5,%6,%7}, {%8,%9}, {%0,%1,%2,%3};"
        : "+f"(c[0]), "+f"(c[1]), "+f"(c[2]), "+f"(c[3])
        : "r"(a[0]), "r"(a[1]), "r"(a[2]), "r"(a[3]), "r"(b0), "r"(b1));
}

template<int DO_GELU, int DO_RES, int OUT_HALF>
__device__ __forceinline__ void gemm_core(
    const __half* __restrict__ A, const __half* __restrict__ B,
    const float* __restrict__ bias, const float* __restrict__ res,
    void* __restrict__ Cout, int N, int K, int m0, int n0)
{
    __shared__ __align__(128) uint4 As4[3][512];   /* 3 stages x 8KB */
    __shared__ __align__(128) uint4 Bs4[3][512];

    int tid = threadIdx.x, lane = tid & 31, wid = tid >> 5;
    int wm = wid >> 2, wn = wid & 3;
    int gid = lane >> 2, tig = lane & 3;

    int r  = tid >> 1;
    int cp = (tid & 1) * 2;
    const __half* ap = A + (long)(m0 + r)*K + cp*8;
    const __half* bp = B + (long)(n0 + r)*K + cp*8;
    int sw  = (r >> 1) & 3;
    int sA0 = r*4 + (cp ^ sw), sA1 = r*4 + ((cp+1) ^ sw);
    uint32_t dA0 = (uint32_t)__cvta_generic_to_shared(&As4[0][sA0]);
    uint32_t dA1 = (uint32_t)__cvta_generic_to_shared(&As4[0][sA1]);
    uint32_t dB0 = (uint32_t)__cvta_generic_to_shared(&Bs4[0][sA0]);
    uint32_t dB1 = (uint32_t)__cvta_generic_to_shared(&Bs4[0][sA1]);

    uint32_t a_addr[4], b_addr[2];
    {
        int rr = (lane & 15), ch = (lane >> 4);
        #pragma unroll
        for (int mt = 0; mt < 4; mt++) {
            int row = wm*64 + mt*16 + rr;
            a_addr[mt] = (uint32_t)__cvta_generic_to_shared(
                &As4[0][row*4 + (ch ^ ((row>>1)&3))]);
        }
        #pragma unroll
        for (int nt2 = 0; nt2 < 2; nt2++) {
            int row = wn*32 + nt2*16 + rr;
            b_addr[nt2] = (uint32_t)__cvta_generic_to_shared(
                &Bs4[0][row*4 + (ch ^ ((row>>1)&3))]);
        }
    }

    float acc[4][4][4];
    #pragma unroll
    for (int i = 0; i < 4; i++)
        #pragma unroll
        for (int j = 0; j < 4; j++)
            acc[i][j][0]=acc[i][j][1]=acc[i][j][2]=acc[i][j][3]=0.f;

    int nit = K >> 5;
    {
        CP16(dA0, ap);            CP16(dA1, ap + 8);
        CP16(dB0, bp);            CP16(dB1, bp + 8);
        CP_COMMIT();
        CP16(dA0 + 8192, ap + 32); CP16(dA1 + 8192, ap + 40);
        CP16(dB0 + 8192, bp + 32); CP16(dB1 + 8192, bp + 40);
        CP_COMMIT();
    }

    int st = 0, stw = 2;
    for (int it = 0; it < nit; it++) {
        CP_WAIT1();
        __syncthreads();
        if (it + 2 < nit) {
            const __half* an = ap + (it+2)*32;
            const __half* bn = bp + (it+2)*32;
            uint32_t so = (uint32_t)(stw * 8192);
            CP16(dA0 + so, an); CP16(dA1 + so, an + 8);
            CP16(dB0 + so, bn); CP16(dB1 + so, bn + 8);
        }
        CP_COMMIT();

        uint32_t coff = (uint32_t)(st * 8192);
        #pragma unroll
        for (int ks = 0; ks < 2; ks++) {
            uint32_t kb = (uint32_t)(ks * 32);
            uint32_t af[4][4], bf[4][2];
            #pragma unroll
            for (int mt = 0; mt < 4; mt++)
                LDSM4(af[mt][0], af[mt][1], af[mt][2], af[mt][3],
                      (a_addr[mt] + coff) ^ kb);
            #pragma unroll
            for (int nt2 = 0; nt2 < 2; nt2++) {
                uint32_t r0,r1,r2,r3;
                LDSM4(r0, r1, r2, r3, (b_addr[nt2] + coff) ^ kb);
                bf[nt2*2+0][0] = r0; bf[nt2*2+0][1] = r2;
                bf[nt2*2+1][0] = r1; bf[nt2*2+1][1] = r3;
            }
            #pragma unroll
            for (int mt = 0; mt < 4; mt++)
                #pragma unroll
                for (int nt = 0; nt < 4; nt++)
                    mma_f16(acc[mt][nt], af[mt], bf[nt][0], bf[nt][1]);
        }
        st  = (st  == 2) ? 0 : st  + 1;
        stw = (stw == 2) ? 0 : stw + 1;
    }

    /* epilogue */
    #pragma unroll
    for (int mt = 0; mt < 4; mt++) {
        int r0r = m0 + wm*64 + mt*16 + gid;
        #pragma unroll
        for (int nt = 0; nt < 4; nt++) {
            int cb = n0 + wn*32 + nt*8 + tig*2;
            float bb0 = bias[cb], bb1 = bias[cb+1];
            float v00 = acc[mt][nt][0] + bb0, v01 = acc[mt][nt][1] + bb1;
            float v10 = acc[mt][nt][2] + bb0, v11 = acc[mt][nt][3] + bb1;
            if (DO_GELU) {
                v00 = 0.5f*v00*(1.0f + erff(v00*0.70710678118654752f));
                v01 = 0.5f*v01*(1.0f + erff(v01*0.70710678118654752f));
                v10 = 0.5f*v10*(1.0f + erff(v10*0.70710678118654752f));
                v11 = 0.5f*v11*(1.0f + erff(v11*0.70710678118654752f));
            }
            long o0 = (long)r0r*N + cb;
            long o1 = (long)(r0r+8)*N + cb;
            if (DO_RES) {
                float2 q0 = *(const float2*)(res + o0);
                float2 q1 = *(const float2*)(res + o1);
                v00 += q0.x; v01 += q0.y; v10 += q1.x; v11 += q1.y;
            }
            if (OUT_HALF) {
                __half2* Ch = (__half2*)Cout;
                Ch[o0 >> 1] = __floats2half2_rn(v00, v01);
                Ch[o1 >> 1] = __floats2half2_rn(v10, v11);
            } else {
                float* Cf = (float*)Cout;
                *(float2*)(Cf + o0) = make_float2(v00, v01);
                *(float2*)(Cf + o1) = make_float2(v10, v11);
            }
        }
    }
}

template<int DO_GELU, int DO_RES, int OUT_HALF>
__global__ __launch_bounds__(256,2) void hgemm(
    const __half* __restrict__ A, const __half* __restrict__ B,
    const float* __restrict__ bias, const float* __restrict__ res,
    void* __restrict__ Cout, int N, int K)
{
    gemm_core<DO_GELU,DO_RES,OUT_HALF>(A, B, bias, res, Cout, N, K,
                                       blockIdx.y << 7, blockIdx.x << 7);
}

/* batched kv projections for 3 layers (half output): 1260 blocks.     */
__global__ __launch_bounds__(256,2) void hgemm_kv(
    const __half* __restrict__ memory,
    const __half* __restrict__ wca_all,
    const float* __restrict__ ca_b,
    __half* __restrict__ kv3,
    int l0)
{
    int bx = blockIdx.x;
    int l  = bx / 420, rr = bx - l*420;
    int n0 = (rr % 6) << 7, m0 = (rr / 6) << 7;
    const __half* B   = wca_all + (long)(l0+l)*1152*DD + (long)384*DD;
    const float*  bb  = ca_b + (l0+l)*1152 + 384;
    __half* C = kv3 + (long)l*MM*768;
    gemm_core<0,0,1>(memory, B, bb, (const float*)0, C, 768, DD, m0, n0);
}

/* ------------------------------------------------------------------ */
/* 6) attention: 4 warps/block, one (seq,head) per warp; half in/out.  */
/* ------------------------------------------------------------------ */
__global__ __launch_bounds__(128) void attn_kernel(
    const __half* __restrict__ qp, int qld,
    const __half* __restrict__ kp, int kld,
    const __half* __restrict__ vp, int vld,
    __half* __restrict__ op)
{
    __shared__ __align__(16) float sq [4][SS*HDD];
    __shared__ __align__(16) float sk [4][SS*HDD];
    __shared__ __align__(16) float svv[4][SS*HDD];
    __shared__ float sc[4][SS*16];
    int w    = threadIdx.x >> 5;
    int lane = threadIdx.x & 31;
    int pair = blockIdx.x*4 + w;
    int seq  = pair >> 3, h = pair & 7;
    int base = seq*SS;
    int hoff = h*HDD;

    for (int i2 = lane; i2 < SS*HDD/2; i2 += 32) {
        int e2 = i2*2;
        int t = e2 / HDD, e = e2 - t*HDD;
        float2 fq = __half22float2(*(const __half2*)(qp + (long)(base+t)*qld + hoff + e));
        float2 fk = __half22float2(*(const __half2*)(kp + (long)(base+t)*kld + hoff + e));
        float2 fv = __half22float2(*(const __half2*)(vp + (long)(base+t)*vld + hoff + e));
        sq [w][t*HDD+e] = fq.x; sq [w][t*HDD+e+1] = fq.y;
        sk [w][t*HDD+e] = fk.x; sk [w][t*HDD+e+1] = fk.y;
        svv[w][t*HDD+e] = fv.x; svv[w][t*HDD+e+1] = fv.y;
    }
    __syncwarp();

    const float scale = 0.14433756729740644f;   /* 1/sqrt(48) */
    for (int i = lane; i < SS*SS; i += 32) {
        int t = i / SS, u = i - t*SS;
        const float4* a4 = (const float4*)(sq[w] + t*HDD);
        const float4* b4 = (const float4*)(sk[w] + u*HDD);
        float s = 0.f;
        #pragma unroll
        for (int g = 0; g < 12; g++) {
            float4 a = a4[g], b = b4[g];
            s = fmaf(a.x,b.x,s); s = fmaf(a.y,b.y,s);
            s = fmaf(a.z,b.z,s); s = fmaf(a.w,b.w,s);
        }
        sc[w][t*16 + u] = s * scale;
    }
    __syncwarp();

    if (lane < SS) {
        float m = -3.4e38f;
        #pragma unroll
        for (int u = 0; u < SS; u++) m = fmaxf(m, sc[w][lane*16+u]);
        float sum = 0.f;
        #pragma unroll
        for (int u = 0; u < SS; u++) {
            float e = expf(sc[w][lane*16+u] - m);
            sc[w][lane*16+u] = e; sum += e;
        }
        float inv = 1.0f/sum;
        #pragma unroll
        for (int u = 0; u < SS; u++) sc[w][lane*16+u] *= inv;
    }
    __syncwarp();

    for (int i = lane; i < SS*HDD; i += 32) {
        int t = i / HDD, e = i - t*HDD;
        float o = 0.f;
        #pragma unroll
        for (int u = 0; u < SS; u++)
            o = fmaf(sc[w][t*16+u], svv[w][u*HDD+e], o);
        op[(long)(base+t)*DD + hoff + e] = __float2half(o);
    }
}

/* ------------------------------------------------------------------ */
/* host orchestration (fork/join streams for independent work)         */
/* ------------------------------------------------------------------ */
extern "C" void kernel_launch(void* const* d_in, const int* in_sizes, int n_in,
                              void* d_out, int out_size)
{
    const float* qt    = (const float*)d_in[0];
    const float* nd    = (const float*)d_in[1];
    const float* sa_w  = (const float*)d_in[2];
    const float* sa_b  = (const float*)d_in[3];
    const float* sa_ow = (const float*)d_in[4];
    const float* sa_ob = (const float*)d_in[5];
    const float* ca_w  = (const float*)d_in[6];
    const float* ca_b  = (const float*)d_in[7];
    const float* ca_ow = (const float*)d_in[8];
    const float* ca_ob = (const float*)d_in[9];
    const float* ln1w  = (const float*)d_in[10];
    const float* ln1b  = (const float*)d_in[11];
    const float* ln2w  = (const float*)d_in[12];
    const float* ln2b  = (const float*)d_in[13];
    const float* ln3w  = (const float*)d_in[14];
    const float* ln3b  = (const float*)d_in[15];
    const float* f1w   = (const float*)d_in[16];
    const float* f1b   = (const float*)d_in[17];
    const float* f2w   = (const float*)d_in[18];
    const float* f2b   = (const float*)d_in[19];
    const float* fnw   = (const float*)d_in[20];
    const float* fnb   = (const float*)d_in[21];
    float* out = (float*)d_out;

    float *sim,*x; int* idx;
    __half *hh,*aoh,*qh,*memh,*mem2h,*ffh,*qkvh,*kv3h;
    __half *wsa,*wso,*wca,*wco,*wf1,*wf2;
    cudaGetSymbolAddress((void**)&sim,   g_sim);
    cudaGetSymbolAddress((void**)&idx,   g_idx);
    cudaGetSymbolAddress((void**)&x,     g_x);
    cudaGetSymbolAddress((void**)&hh,    g_hh);
    cudaGetSymbolAddress((void**)&aoh,   g_aoh);
    cudaGetSymbolAddress((void**)&qh,    g_qh);
    cudaGetSymbolAddress((void**)&memh,  g_memh);
    cudaGetSymbolAddress((void**)&mem2h, g_mem2h);
    cudaGetSymbolAddress((void**)&ffh,   g_ffh);
    cudaGetSymbolAddress((void**)&qkvh,  g_qkvh);
    cudaGetSymbolAddress((void**)&kv3h,  g_kv3h);
    cudaGetSymbolAddress((void**)&wsa,   g_wsa);
    cudaGetSymbolAddress((void**)&wso,   g_wso);
    cudaGetSymbolAddress((void**)&wca,   g_wca);
    cudaGetSymbolAddress((void**)&wco,   g_wco);
    cudaGetSymbolAddress((void**)&wf1,   g_wf1);
    cudaGetSymbolAddress((void**)&wf2,   g_wf2);

    /* side streams + fork/join events (host-side only; not on replay path) */
    cudaStream_t s1, s2;
    cudaStreamCreateWithFlags(&s1, cudaStreamNonBlocking);
    cudaStreamCreateWithFlags(&s2, cudaStreamNonBlocking);
    cudaEvent_t evFork, evCvt, evBuild, evKV0, evSnap, evKV3;
    cudaEventCreateWithFlags(&evFork,  cudaEventDisableTiming);
    cudaEventCreateWithFlags(&evCvt,   cudaEventDisableTiming);
    cudaEventCreateWithFlags(&evBuild, cudaEventDisableTiming);
    cudaEventCreateWithFlags(&evKV0,   cudaEventDisableTiming);
    cudaEventCreateWithFlags(&evSnap,  cudaEventDisableTiming);
    cudaEventCreateWithFlags(&evKV3,   cudaEventDisableTiming);

    /* fork: weight conversion runs on s1, overlapped with retrieval */
    cudaEventRecord(evFork, 0);
    cudaStreamWaitEvent(s1, evFork, 0);
    cvtall_kernel<<<(CVT_TOTAL + 255)/256, 256, 0, s1>>>(
        sa_w, sa_ow, ca_w, ca_ow, f1w, f2w);
    cudaEventRecord(evCvt, s1);

    /* stage A: retrieval (default stream) */
    sim_kernel  <<<dim3(16,64), 128>>>(qt, nd, sim);
    topk_kernel <<<BB*SS, 256>>>(sim, idx);
    build_kernel<<<3360, 256>>>(qt, nd, idx, x, memh);
    cudaEventRecord(evBuild, 0);

    /* s2: kv projections layers 0-2 (needs memh + converted wca) */
    cudaStreamWaitEvent(s2, evBuild, 0);
    cudaStreamWaitEvent(s2, evCvt, 0);
    hgemm_kv<<<1260, 256, 0, s2>>>(memh, wca, ca_b, kv3h, 0);
    cudaEventRecord(evKV0, s2);

    /* default stream needs converted weights before first hgemm */
    cudaStreamWaitEvent(0, evCvt, 0);

    /* stage B: 6 decoder blocks */
    for (int i = 0; i < 6; i++) {
        __half* kvl = kv3h + (long)(i % 3)*MM*768;

        /* self-attention */
        ln_kernel<1><<<560,256>>>(x, ln1w + i*DD, ln1b + i*DD, hh, (__half*)0);
        hgemm<0,0,1><<<dim3(9,70),256>>>(hh, wsa + (long)i*1152*DD,
                                         sa_b + i*1152, (const float*)0,
                                         qkvh, 1152, DD);
        attn_kernel<<<1280,128>>>(qkvh,1152, qkvh+384,1152, qkvh+768,1152, aoh);
        hgemm<0,1,0><<<dim3(3,70),256>>>(aoh, wso + (long)i*DD*DD,
                                         sa_ob + i*DD, x, x, DD, DD);

        /* cross-attention: q projection (kv computed on s2) */
        ln_kernel<1><<<560,256>>>(x, ln2w + i*DD, ln2b + i*DD, hh, (__half*)0);
        hgemm<0,0,1><<<dim3(3,70),256>>>(hh, wca + (long)i*1152*DD,
                                         ca_b + i*1152, (const float*)0,
                                         qh, DD, DD);
        if (i == 0) cudaStreamWaitEvent(0, evKV0, 0);   /* join kv 0-2 */
        if (i == 3) cudaStreamWaitEvent(0, evKV3, 0);   /* join kv 3-5 */
        attn_kernel<<<1280,128>>>(qh,384, kvl,768, kvl+384,768, aoh);
        hgemm<0,1,0><<<dim3(3,70),256>>>(aoh, wco + (long)i*DD*DD,
                                         ca_ob + i*DD, x, x, DD, DD);

        /* FFN */
        ln_kernel<1><<<560,256>>>(x, ln3w + i*DD, ln3b + i*DD, hh, (__half*)0);
        hgemm<1,0,1><<<dim3(12,70),256>>>(hh, wf1 + (long)i*1536*DD,
                                          f1b + i*1536, (const float*)0,
                                          ffh, 1536, DD);
        hgemm<0,1,0><<<dim3(3,70),256>>>(ffh, wf2 + (long)i*DD*1536,
                                         f2b + i*DD, x, x, DD, 1536);

        /* mid-stack snapshot; kv projections for layers 3-5 fork to s2 */
        if (i == 2) {
            ln_kernel<2><<<560,256>>>(x, fnw, fnb, x, mem2h);
            cudaEventRecord(evSnap, 0);
            cudaStreamWaitEvent(s2, evSnap, 0);
            hgemm_kv<<<1260, 256, 0, s2>>>(mem2h, wca, ca_b, kv3h, 3);
            cudaEventRecord(evKV3, s2);
        }
    }

    /* final norm straight into d_out (f32) */
    ln_kernel<0><<<560,256>>>(x, fnw + DD, fnb + DD, out, (__half*)0);

    cudaEventDestroy(evFork);  cudaEventDestroy(evCvt);
    cudaEventDestroy(evBuild); cudaEventDestroy(evKV0);
    cudaEventDestroy(evSnap);  cudaEventDestroy(evKV3);
    cudaStreamDestroy(s1);
    cudaStreamDestroy(s2);
}